// round 1
// baseline (speedup 1.0000x reference)
#include <cuda_runtime.h>
#include <math.h>

// Problem constants (fixed by the reference setup_inputs)
#define TT 2048      // tokens
#define DD 1024      // model dim (Lorentz, incl. time coord)
#define EE 8         // experts
#define NI 1023      // I-1 == D-1 (space dims)
#define KD 1024      // GEMM K dim (= D = I)

#define ROWS_ROUTED (EE * TT)              // 16384 (bucketed layout e*TT + p)
#define SHARED_BASE ROWS_ROUTED
#define TOTAL_ROWS  (ROWS_ROUTED + TT)     // 18432

// ------------------- device scratch (no allocations allowed) -------------------
__device__ float g_H[(size_t)TOTAL_ROWS * KD];   // [t | sp] per row (stage-1 out)
__device__ float g_O[(size_t)TOTAL_ROWS * KD];   // [ot | o] per row (stage-2 out)
__device__ int   g_cnt[EE];
__device__ int   g_bucket[ROWS_ROUTED];          // expert bucket -> token id
__device__ int   g_rowOf[TT];                    // token -> routed row (e*TT+p)
__device__ float g_wgt[TT];                      // token -> gate weight

// ------------------------------- helpers ---------------------------------------
__device__ __forceinline__ float block_reduce_sum(float v) {
    __shared__ float red[32];
    int lane = threadIdx.x & 31, w = threadIdx.x >> 5;
    #pragma unroll
    for (int o = 16; o; o >>= 1) v += __shfl_down_sync(0xffffffffu, v, o);
    if (lane == 0) red[w] = v;
    __syncthreads();
    int nw = (blockDim.x + 31) >> 5;
    v = (threadIdx.x < nw) ? red[threadIdx.x] : 0.0f;
    if (w == 0) {
        #pragma unroll
        for (int o = 16; o; o >>= 1) v += __shfl_down_sync(0xffffffffu, v, o);
        if (lane == 0) red[0] = v;
    }
    __syncthreads();
    return red[0];
}

// ------------------------------- kernels ---------------------------------------
__global__ void zero_cnt_kernel() {
    if (threadIdx.x < EE) g_cnt[threadIdx.x] = 0;
}

// One block (256 threads = 8 warps) per token. Warp w computes logit for expert w.
__global__ void gate_kernel(const float* __restrict__ x,
                            const float* __restrict__ gate_w,
                            const float* __restrict__ gate_b) {
    int t = blockIdx.x;
    int tid = threadIdx.x;
    int w = tid >> 5, lane = tid & 31;
    __shared__ float s_logit[EE];
    const float* xr = x + (size_t)t * DD + 1;      // x[:,1:]
    const float* gr = gate_w + (size_t)w * NI;
    float s = 0.0f;
    for (int j = lane; j < NI; j += 32) s += xr[j] * gr[j];
    #pragma unroll
    for (int o = 16; o; o >>= 1) s += __shfl_down_sync(0xffffffffu, s, o);
    if (lane == 0) s_logit[w] = s;
    __syncthreads();
    if (tid == 0) {
        float m = s_logit[0];
        #pragma unroll
        for (int e = 1; e < EE; e++) m = fmaxf(m, s_logit[e]);
        float ex[EE], den = 0.0f;
        #pragma unroll
        for (int e = 0; e < EE; e++) { ex[e] = expf(s_logit[e] - m); den += ex[e]; }
        float inv = 1.0f / den;
        float best = -1e30f; int bi = 0;
        #pragma unroll
        for (int e = 0; e < EE; e++) {
            float biased = ex[e] * inv + gate_b[e];
            if (biased > best) { best = biased; bi = e; }   // strict > == lowest-idx ties
        }
        g_wgt[t] = ex[bi] * inv;
        int p = atomicAdd(&g_cnt[bi], 1);
        g_bucket[bi * TT + p] = t;
        g_rowOf[t] = bi * TT + p;
    }
}

// Stage-1 dual GEMM:  SP = silu(X W1^T) * (X W3^T)   (NT, K=1024, N=1023)
// grid = (16 n-tiles, 32 m-tiles, 9 "experts"); z==8 -> shared expert on all tokens.
__global__ __launch_bounds__(256) void gemm1_kernel(
    const float* __restrict__ x,
    const float* __restrict__ W1, const float* __restrict__ W3,
    const float* __restrict__ Ws1, const float* __restrict__ Ws3)
{
    int e = blockIdx.z;
    int cnt; const float *w1p, *w3p; int rowBase;
    if (e < EE) {
        cnt = g_cnt[e];
        w1p = W1 + (size_t)e * NI * KD;
        w3p = W3 + (size_t)e * NI * KD;
        rowBase = e * TT;
    } else {
        cnt = TT; w1p = Ws1; w3p = Ws3; rowBase = SHARED_BASE;
    }
    int m0 = blockIdx.y * 64;
    if (m0 >= cnt) return;
    int n0 = blockIdx.x * 64;

    __shared__ float Xs[16][64];
    __shared__ float B1s[16][64];
    __shared__ float B3s[16][64];
    __shared__ int   toks[64];

    int tid = threadIdx.x;
    if (tid < 64) {
        int p = m0 + tid;
        toks[tid] = (p < cnt) ? ((e < EE) ? g_bucket[e * TT + p] : p) : -1;
    }
    __syncthreads();

    int lm = tid >> 2;     // 0..63 : row within tile (for loads)
    int lc = tid & 3;      // which float4 chunk along k
    int tm = tid >> 4;     // 0..15 : 4-row group (compute)
    int tn = tid & 15;     // 0..15 : 4-col group (compute)

    float acc1[4][4], acc3[4][4];
    #pragma unroll
    for (int i = 0; i < 4; i++)
        #pragma unroll
        for (int j = 0; j < 4; j++) { acc1[i][j] = 0.0f; acc3[i][j] = 0.0f; }

    for (int k0 = 0; k0 < KD; k0 += 16) {
        int tok = toks[lm];
        float4 xv = make_float4(0.f, 0.f, 0.f, 0.f);
        if (tok >= 0) xv = *(const float4*)(x + (size_t)tok * DD + k0 + lc * 4);
        Xs[lc*4+0][lm] = xv.x; Xs[lc*4+1][lm] = xv.y;
        Xs[lc*4+2][lm] = xv.z; Xs[lc*4+3][lm] = xv.w;

        int n = n0 + lm;
        float4 b1 = make_float4(0.f, 0.f, 0.f, 0.f);
        float4 b3 = make_float4(0.f, 0.f, 0.f, 0.f);
        if (n < NI) {
            b1 = *(const float4*)(w1p + (size_t)n * KD + k0 + lc * 4);
            b3 = *(const float4*)(w3p + (size_t)n * KD + k0 + lc * 4);
        }
        B1s[lc*4+0][lm] = b1.x; B1s[lc*4+1][lm] = b1.y;
        B1s[lc*4+2][lm] = b1.z; B1s[lc*4+3][lm] = b1.w;
        B3s[lc*4+0][lm] = b3.x; B3s[lc*4+1][lm] = b3.y;
        B3s[lc*4+2][lm] = b3.z; B3s[lc*4+3][lm] = b3.w;
        __syncthreads();

        #pragma unroll
        for (int kk = 0; kk < 16; kk++) {
            float4 av  = *(const float4*)&Xs[kk][tm * 4];
            float4 v1  = *(const float4*)&B1s[kk][tn * 4];
            float4 v3  = *(const float4*)&B3s[kk][tn * 4];
            float a_[4]  = {av.x, av.y, av.z, av.w};
            float b1_[4] = {v1.x, v1.y, v1.z, v1.w};
            float b3_[4] = {v3.x, v3.y, v3.z, v3.w};
            #pragma unroll
            for (int i = 0; i < 4; i++)
                #pragma unroll
                for (int j = 0; j < 4; j++) {
                    acc1[i][j] = fmaf(a_[i], b1_[j], acc1[i][j]);
                    acc3[i][j] = fmaf(a_[i], b3_[j], acc3[i][j]);
                }
        }
        __syncthreads();
    }

    #pragma unroll
    for (int i = 0; i < 4; i++) {
        int p = m0 + tm * 4 + i;
        if (p >= cnt) continue;
        float* hrow = g_H + (size_t)(rowBase + p) * KD;
        #pragma unroll
        for (int j = 0; j < 4; j++) {
            int c = n0 + tn * 4 + j;
            if (c < NI) {
                float v1 = acc1[i][j];
                float sig = 1.0f / (1.0f + expf(-v1));
                hrow[1 + c] = v1 * sig * acc3[i][j];
            }
        }
    }
}

// norm kernel: which==0 -> H[row][0] = sqrt(sum_{c>=1} H^2 + 1);  which==1 -> same on O.
// grid = 2*TT blocks: b < TT -> routed row rowOf[b]; else shared row.
__global__ void norm_kernel(int which) {
    int b = blockIdx.x;
    int row = (b < TT) ? g_rowOf[b] : (SHARED_BASE + (b - TT));
    float* base = which ? g_O : g_H;
    float* r = base + (size_t)row * KD;
    float s = 0.0f;
    for (int c = 1 + threadIdx.x; c < KD; c += blockDim.x) {
        float v = r[c]; s += v * v;
    }
    float tot = block_reduce_sum(s);
    if (threadIdx.x == 0) r[0] = sqrtf(tot + 1.0f);   // c_mid = c_out = 1; clip dead
}

// Stage-2 GEMM:  O = H W2^T  (NT, K=1024 incl. time col, N=1023)
__global__ __launch_bounds__(256) void gemm2_kernel(
    const float* __restrict__ W2, const float* __restrict__ Ws2)
{
    int e = blockIdx.z;
    int cnt; const float* wp; int rowBase;
    if (e < EE) { cnt = g_cnt[e]; wp = W2 + (size_t)e * NI * KD; rowBase = e * TT; }
    else        { cnt = TT;       wp = Ws2;                      rowBase = SHARED_BASE; }
    int m0 = blockIdx.y * 64;
    if (m0 >= cnt) return;
    int n0 = blockIdx.x * 64;

    __shared__ float As[16][64];
    __shared__ float Bs[16][64];

    int tid = threadIdx.x;
    int lm = tid >> 2, lc = tid & 3;
    int tm = tid >> 4, tn = tid & 15;

    float acc[4][4];
    #pragma unroll
    for (int i = 0; i < 4; i++)
        #pragma unroll
        for (int j = 0; j < 4; j++) acc[i][j] = 0.0f;

    for (int k0 = 0; k0 < KD; k0 += 16) {
        int p = m0 + lm;
        float4 av = make_float4(0.f, 0.f, 0.f, 0.f);
        if (p < cnt) av = *(const float4*)(g_H + (size_t)(rowBase + p) * KD + k0 + lc * 4);
        As[lc*4+0][lm] = av.x; As[lc*4+1][lm] = av.y;
        As[lc*4+2][lm] = av.z; As[lc*4+3][lm] = av.w;

        int n = n0 + lm;
        float4 bv = make_float4(0.f, 0.f, 0.f, 0.f);
        if (n < NI) bv = *(const float4*)(wp + (size_t)n * KD + k0 + lc * 4);
        Bs[lc*4+0][lm] = bv.x; Bs[lc*4+1][lm] = bv.y;
        Bs[lc*4+2][lm] = bv.z; Bs[lc*4+3][lm] = bv.w;
        __syncthreads();

        #pragma unroll
        for (int kk = 0; kk < 16; kk++) {
            float4 a4 = *(const float4*)&As[kk][tm * 4];
            float4 b4 = *(const float4*)&Bs[kk][tn * 4];
            float a_[4] = {a4.x, a4.y, a4.z, a4.w};
            float b_[4] = {b4.x, b4.y, b4.z, b4.w};
            #pragma unroll
            for (int i = 0; i < 4; i++)
                #pragma unroll
                for (int j = 0; j < 4; j++)
                    acc[i][j] = fmaf(a_[i], b_[j], acc[i][j]);
        }
        __syncthreads();
    }

    #pragma unroll
    for (int i = 0; i < 4; i++) {
        int p = m0 + tm * 4 + i;
        if (p >= cnt) continue;
        float* orow = g_O + (size_t)(rowBase + p) * KD;
        #pragma unroll
        for (int j = 0; j < 4; j++) {
            int c = n0 + tn * 4 + j;
            if (c < NI) orow[1 + c] = acc[i][j];
        }
    }
}

// Per-token: comb = z + 2*(y0 + w*e_out); Lorentz-normalize.
__global__ void combine_kernel(float* __restrict__ out) {
    int t = blockIdx.x;
    int tid = threadIdx.x;                  // 256 threads, 4 dims each
    int rr = g_rowOf[t];
    float wgt = g_wgt[t];
    const float* zr = g_O + (size_t)(SHARED_BASE + t) * KD;
    const float* er = g_O + (size_t)rr * KD;

    float comb[4];
    float ss = 0.0f;
    #pragma unroll
    for (int i = 0; i < 4; i++) {
        int d = tid + i * 256;
        float y = (d == 0) ? (1.0f + wgt * er[0])       // y0 time coord = sqrt(C)=1
                           : (wgt * er[d]);
        float c = zr[d] + 2.0f * y;                     // SCALE = 2
        comb[i] = c;
        if (d != 0) ss += c * c;
    }
    float space_sq = block_reduce_sum(ss);
    float comb0 = zr[0] + 2.0f * (1.0f + wgt * er[0]);  // recomputed by all threads
    float li = space_sq - comb0 * comb0;
    float scale = rsqrtf(fmaxf(fabsf(li), 1e-8f));      // sqrt(C)=1
    #pragma unroll
    for (int i = 0; i < 4; i++) {
        int d = tid + i * 256;
        out[(size_t)t * DD + d] = comb[i] * scale;
    }
}

// ------------------------------- launcher --------------------------------------
extern "C" void kernel_launch(void* const* d_in, const int* in_sizes, int n_in,
                              void* d_out, int out_size) {
    const float* x      = (const float*)d_in[0];
    const float* gate_w = (const float*)d_in[1];
    const float* gate_b = (const float*)d_in[2];
    const float* W1     = (const float*)d_in[3];
    const float* W3     = (const float*)d_in[4];
    const float* W2     = (const float*)d_in[5];
    const float* Ws1    = (const float*)d_in[6];
    const float* Ws3    = (const float*)d_in[7];
    const float* Ws2    = (const float*)d_in[8];
    float* out = (float*)d_out;

    zero_cnt_kernel<<<1, 32>>>();
    gate_kernel<<<TT, 256>>>(x, gate_w, gate_b);
    gemm1_kernel<<<dim3(16, 32, 9), 256>>>(x, W1, W3, Ws1, Ws3);
    norm_kernel<<<2 * TT, 256>>>(0);
    gemm2_kernel<<<dim3(16, 32, 9), 256>>>(W2, Ws2);
    norm_kernel<<<2 * TT, 256>>>(1);
    combine_kernel<<<TT, 256>>>(out);
}

// round 3
// speedup vs baseline: 2.9468x; 2.9468x over previous
#include <cuda_runtime.h>
#include <math.h>
#include <stdint.h>

// Problem constants (fixed by the reference setup_inputs)
#define TT 2048      // tokens
#define DD 1024      // model dim (Lorentz, incl. time coord)
#define EE 8         // experts
#define NI 1023      // I-1 == D-1 (space dims)
#define KD 1024      // GEMM K dim (= D = I)

#define ROWS_ROUTED (EE * TT)
#define SHARED_BASE ROWS_ROUTED
#define TOTAL_ROWS  (ROWS_ROUTED + TT)

// tcgen05 only exists in arch-specific ('a') compilation passes.
#if defined(__CUDA_ARCH_FEAT_SM103_ALL) || defined(__CUDA_ARCH_FEAT_SM100_ALL) || defined(__CUDA_ARCH_FEAT_SM101_ALL)
#define HAS_TCGEN05 1
#else
#define HAS_TCGEN05 0
#endif

// ------------------- device scratch (no allocations allowed) -------------------
__device__ float g_H[(size_t)TOTAL_ROWS * KD];
__device__ float g_O[(size_t)TOTAL_ROWS * KD];
__device__ int   g_cnt[EE];
__device__ int   g_bucket[ROWS_ROUTED];
__device__ int   g_rowOf[TT];
__device__ float g_wgt[TT];

// ------------------------------ helpers -----------------------------------------
__device__ __forceinline__ uint32_t smem_to_u32(const void* p) {
    uint32_t a;
    asm("{ .reg .u64 t; cvta.to.shared.u64 t, %1; cvt.u32.u64 %0, t; }" : "=r"(a) : "l"(p));
    return a;
}
__device__ __forceinline__ uint32_t f2tf32(float f) {
    uint32_t o; asm("cvt.rna.tf32.f32 %0, %1;" : "=r"(o) : "f"(f)); return o;
}
__device__ __forceinline__ float silu_mul(float v1, float v3) {
    return v1 * v3 / (1.0f + expf(-v1));
}

#if HAS_TCGEN05
__device__ __forceinline__ uint32_t elect_one_pred() {
    uint32_t pred;
    asm volatile("{\n\t.reg .pred p;\n\telect.sync _|p, 0xFFFFFFFF;\n\t"
                 "selp.b32 %0, 1, 0, p;\n\t}" : "=r"(pred));
    return pred;
}
#define TCGEN05_ALLOC(smem_result_addr, nCols) \
    asm volatile("tcgen05.alloc.cta_group::1.sync.aligned.shared::cta.b32 [%0], %1;" \
        :: "r"((uint32_t)(smem_result_addr)), "r"((uint32_t)(nCols)) : "memory")
#define TCGEN05_DEALLOC(tmem_addr, nCols) \
    asm volatile("tcgen05.dealloc.cta_group::1.sync.aligned.b32 %0, %1;" \
        :: "r"(tmem_addr), "r"((uint32_t)(nCols)))
#define TCGEN05_COMMIT(mbar_smem_addr) \
    asm volatile("tcgen05.commit.cta_group::1.mbarrier::arrive::one.shared::cluster.b64 [%0];" \
        :: "r"((uint32_t)(mbar_smem_addr)) : "memory")
#define TCGEN05_WAIT_LD() asm volatile("tcgen05.wait::ld.sync.aligned;" ::: "memory")
#define TCGEN05_FENCE_AFTER() asm volatile("tcgen05.fence::after_thread_sync;" ::: "memory")
#define FENCE_PROXY_ASYNC_SHARED_CTA() asm volatile("fence.proxy.async.shared::cta;" ::: "memory")
#define MBARRIER_INIT(mbar, count) \
    asm volatile("mbarrier.init.shared.b64 [%0], %1;" \
        :: "r"((uint32_t)(mbar)), "r"((uint32_t)(count)) : "memory")
#define MBARRIER_WAIT_PARITY(mbar_smem_addr, phase_parity) do { \
    uint32_t _mbar = (uint32_t)(mbar_smem_addr); \
    uint32_t _parity = (uint32_t)(phase_parity); \
    uint32_t _done; \
    asm volatile("{\n\t.reg .pred p;\n\t" \
        "mbarrier.try_wait.parity.acquire.cta.shared::cta.b64 p, [%1], %2;\n\t" \
        "selp.b32 %0, 1, 0, p;\n\t}" : "=r"(_done) : "r"(_mbar), "r"(_parity) : "memory"); \
    if (!_done) { \
        asm volatile("{\n\t.reg .pred P1;\n\t" \
            "WAIT_LOOP_%=:\n\t" \
            "mbarrier.try_wait.parity.acquire.cta.shared::cta.b64 P1, [%0], %1, 0x989680;\n\t" \
            "@P1 bra.uni WAIT_DONE_%=;\n\t" \
            "bra.uni WAIT_LOOP_%=;\n\t" \
            "WAIT_DONE_%=:\n\t}" :: "r"(_mbar), "r"(_parity) : "memory"); \
    } \
} while(0)
#define TCGEN05_LD_32X32B_X32(r, tmem_addr) \
    asm volatile("tcgen05.ld.sync.aligned.32x32b.x32.b32 " \
        "{%0, %1, %2, %3, %4, %5, %6, %7, " \
        " %8, %9, %10, %11, %12, %13, %14, %15, " \
        " %16, %17, %18, %19, %20, %21, %22, %23, " \
        " %24, %25, %26, %27, %28, %29, %30, %31}, [%32];" \
        : "=r"((r)[0]),  "=r"((r)[1]),  "=r"((r)[2]),  "=r"((r)[3]), \
          "=r"((r)[4]),  "=r"((r)[5]),  "=r"((r)[6]),  "=r"((r)[7]), \
          "=r"((r)[8]),  "=r"((r)[9]),  "=r"((r)[10]), "=r"((r)[11]), \
          "=r"((r)[12]), "=r"((r)[13]), "=r"((r)[14]), "=r"((r)[15]), \
          "=r"((r)[16]), "=r"((r)[17]), "=r"((r)[18]), "=r"((r)[19]), \
          "=r"((r)[20]), "=r"((r)[21]), "=r"((r)[22]), "=r"((r)[23]), \
          "=r"((r)[24]), "=r"((r)[25]), "=r"((r)[26]), "=r"((r)[27]), \
          "=r"((r)[28]), "=r"((r)[29]), "=r"((r)[30]), "=r"((r)[31]) \
        : "r"(tmem_addr))

static constexpr uint64_t SMEM_DESC_BASE_SW128 =
    (uint64_t(2) << 61) | (uint64_t(1) << 46) | (uint64_t(64) << 32) | (uint64_t(1) << 16);
#define MAKE_SMEM_DESC(base_addr) \
    (SMEM_DESC_BASE_SW128 | ((uint64_t)((base_addr) >> 4) & 0x3FFF))
#define IDESC_TF32_M128_N128 ((1u<<4) | (2u<<7) | (2u<<10) | (16u<<17) | (8u<<24))

__device__ __forceinline__ void mma_tf32_ss(uint32_t d_tmem, uint64_t a_desc,
                                            uint64_t b_desc, uint32_t idesc, bool acc) {
    uint32_t en = acc ? 1u : 0u;
    asm volatile(
        "{\n\t.reg .pred p;\n\tsetp.ne.u32 p, %5, 0;\n\t"
        "tcgen05.mma.cta_group::1.kind::tf32 [%0], %1, %2, %3, {%4, %4, %4, %4}, p;\n\t}"
        :: "r"(d_tmem), "l"(a_desc), "l"(b_desc), "r"(idesc), "r"(0u), "r"(en)
        : "memory");
}
#endif // HAS_TCGEN05

// Portable tf32 mma.sync (sm_80+, legal on plain sm_103)
#define MMA_TF32_SYNC(d, a, b) \
    asm volatile("mma.sync.aligned.m16n8k8.row.col.f32.tf32.tf32.f32 " \
        "{%0,%1,%2,%3}, {%4,%5,%6,%7}, {%8,%9}, {%0,%1,%2,%3};" \
        : "+f"((d)[0]), "+f"((d)[1]), "+f"((d)[2]), "+f"((d)[3]) \
        : "r"((a)[0]), "r"((a)[1]), "r"((a)[2]), "r"((a)[3]), \
          "r"((b)[0]), "r"((b)[1]))

// ------------------------------- small kernels ----------------------------------
__device__ __forceinline__ float block_reduce_sum(float v) {
    __shared__ float red[32];
    int lane = threadIdx.x & 31, w = threadIdx.x >> 5;
    #pragma unroll
    for (int o = 16; o; o >>= 1) v += __shfl_down_sync(0xffffffffu, v, o);
    if (lane == 0) red[w] = v;
    __syncthreads();
    int nw = (blockDim.x + 31) >> 5;
    v = (threadIdx.x < nw) ? red[threadIdx.x] : 0.0f;
    if (w == 0) {
        #pragma unroll
        for (int o = 16; o; o >>= 1) v += __shfl_down_sync(0xffffffffu, v, o);
        if (lane == 0) red[0] = v;
    }
    __syncthreads();
    return red[0];
}

__global__ void zero_cnt_kernel() {
    if (threadIdx.x < EE) g_cnt[threadIdx.x] = 0;
}

__global__ void gate_kernel(const float* __restrict__ x,
                            const float* __restrict__ gate_w,
                            const float* __restrict__ gate_b) {
    int t = blockIdx.x;
    int tid = threadIdx.x;
    int w = tid >> 5, lane = tid & 31;
    __shared__ float s_logit[EE];
    const float* xr = x + (size_t)t * DD + 1;
    const float* gr = gate_w + (size_t)w * NI;
    float s = 0.0f;
    for (int j = lane; j < NI; j += 32) s += xr[j] * gr[j];
    #pragma unroll
    for (int o = 16; o; o >>= 1) s += __shfl_down_sync(0xffffffffu, s, o);
    if (lane == 0) s_logit[w] = s;
    __syncthreads();
    if (tid == 0) {
        float m = s_logit[0];
        #pragma unroll
        for (int e = 1; e < EE; e++) m = fmaxf(m, s_logit[e]);
        float ex[EE], den = 0.0f;
        #pragma unroll
        for (int e = 0; e < EE; e++) { ex[e] = expf(s_logit[e] - m); den += ex[e]; }
        float inv = 1.0f / den;
        float best = -1e30f; int bi = 0;
        #pragma unroll
        for (int e = 0; e < EE; e++) {
            float biased = ex[e] * inv + gate_b[e];
            if (biased > best) { best = biased; bi = e; }
        }
        g_wgt[t] = ex[bi] * inv;
        int p = atomicAdd(&g_cnt[bi], 1);
        g_bucket[bi * TT + p] = t;
        g_rowOf[t] = bi * TT + p;
    }
}

__global__ void norm_kernel(int which) {
    int b = blockIdx.x;
    int row = (b < TT) ? g_rowOf[b] : (SHARED_BASE + (b - TT));
    float* base = which ? g_O : g_H;
    float* r = base + (size_t)row * KD;
    float s = 0.0f;
    for (int c = 1 + threadIdx.x; c < KD; c += blockDim.x) {
        float v = r[c]; s += v * v;
    }
    float tot = block_reduce_sum(s);
    if (threadIdx.x == 0) r[0] = sqrtf(tot + 1.0f);
}

__global__ void combine_kernel(float* __restrict__ out) {
    int t = blockIdx.x;
    int tid = threadIdx.x;
    int rr = g_rowOf[t];
    float wgt = g_wgt[t];
    const float* zr = g_O + (size_t)(SHARED_BASE + t) * KD;
    const float* er = g_O + (size_t)rr * KD;
    float comb[4];
    float ss = 0.0f;
    #pragma unroll
    for (int i = 0; i < 4; i++) {
        int d = tid + i * 256;
        float y = (d == 0) ? (1.0f + wgt * er[0]) : (wgt * er[d]);
        float c = zr[d] + 2.0f * y;
        comb[i] = c;
        if (d != 0) ss += c * c;
    }
    float space_sq = block_reduce_sum(ss);
    float comb0 = zr[0] + 2.0f * (1.0f + wgt * er[0]);
    float li = space_sq - comb0 * comb0;
    float scale = rsqrtf(fmaxf(fabsf(li), 1e-8f));
    #pragma unroll
    for (int i = 0; i < 4; i++) {
        int d = tid + i * 256;
        out[(size_t)t * DD + d] = comb[i] * scale;
    }
}

// ------------------------- GEMM shared smem offsets -----------------------------
// tcgen05 path:
#define SM_TMEM 0
#define SM_MBAR 8
#define SM_TOKS 64
#define SM_A    1024
#define TILEB   16384
#define SM_B1   (SM_A + 2*TILEB)
#define SM_B3   (SM_B1 + 2*TILEB)
#define SMEM1_TOTAL (SM_B3 + 2*TILEB)   // 99328
#define SMEM2_TOTAL (SM_B1 + 2*TILEB)   // 66560
#define NCHUNK 32

// fallback (mma.sync) path: A 128x32 (stride 36), B 64x32 (stride 36)
#define F_ASTR   36
#define F_SM_A   1024
#define F_SM_B1  (F_SM_A  + 128*F_ASTR*4)   // 19456
#define F_SM_B3  (F_SM_B1 + 64*F_ASTR*4)    // 28672

#if HAS_TCGEN05
__device__ __forceinline__ void load_tile_f4(char* smem, uint32_t base,
                                             const float* gsrc, bool valid, int idx) {
    int r = idx >> 3, c4 = idx & 7;
    uint32_t off = (uint32_t)(r * 128 + c4 * 16);
    uint32_t sw = off ^ ((off >> 3) & 0x70);
    float4 v = make_float4(0.f, 0.f, 0.f, 0.f);
    if (valid) v = *(const float4*)(gsrc + c4 * 4);
    *(float4*)(smem + base + sw) = v;
}
#endif

// copy a 32-float-wide row chunk into padded smem, converting to tf32 (rna)
__device__ __forceinline__ void fb_store_tf32(char* smem, uint32_t base, int r, int c4,
                                              const float* gsrc, bool valid) {
    float4 v = make_float4(0.f, 0.f, 0.f, 0.f);
    if (valid) v = *(const float4*)(gsrc + c4 * 4);
    uint4 u;
    u.x = f2tf32(v.x); u.y = f2tf32(v.y); u.z = f2tf32(v.z); u.w = f2tf32(v.w);
    *(uint4*)(smem + base + (size_t)(r * F_ASTR + c4 * 4) * 4) = u;
}

// ------------------------------ GEMM 1 ------------------------------------------
__global__ __launch_bounds__(256) void gemm1_tc(
    const float* __restrict__ x,
    const float* __restrict__ W1, const float* __restrict__ W3,
    const float* __restrict__ Ws1, const float* __restrict__ Ws3)
{
    extern __shared__ char smem[];
    int tid = threadIdx.x;

    int e = blockIdx.z;
    int cnt; const float *w1p, *w3p; int rowBase;
    if (e < EE) {
        cnt = g_cnt[e];
        w1p = W1 + (size_t)e * NI * KD;
        w3p = W3 + (size_t)e * NI * KD;
        rowBase = e * TT;
    } else {
        cnt = TT; w1p = Ws1; w3p = Ws3; rowBase = SHARED_BASE;
    }
    int m0 = blockIdx.y * 128;
    if (m0 >= cnt) return;

#if HAS_TCGEN05
    if (blockIdx.x & 1) return;                 // tc path uses 128-wide n tiles
    int n0 = (blockIdx.x >> 1) * 128;
    uint32_t sb = smem_to_u32(smem);
    int wid = tid >> 5;

    int* toks = (int*)(smem + SM_TOKS);
    if (tid < 128) {
        int p = m0 + tid;
        toks[tid] = (p < cnt) ? ((e < EE) ? g_bucket[e * TT + p] : p) : -1;
    }
    if (wid == 0) TCGEN05_ALLOC(sb + SM_TMEM, 256);
    if (tid == 0) { MBARRIER_INIT(sb + SM_MBAR, 1); MBARRIER_INIT(sb + SM_MBAR + 8, 1); }
    __syncthreads();
    uint32_t tmem;
    asm volatile("ld.shared.b32 %0, [%1];" : "=r"(tmem) : "r"(sb + SM_TMEM));

    for (int c = 0; c < NCHUNK; c++) {
        int buf = c & 1;
        if (c >= 2) MBARRIER_WAIT_PARITY(sb + SM_MBAR + 8 * buf, ((c >> 1) - 1) & 1);
        int k0 = c * 32;
        uint32_t aB  = SM_A  + buf * TILEB;
        uint32_t b1B = SM_B1 + buf * TILEB;
        uint32_t b3B = SM_B3 + buf * TILEB;
        #pragma unroll
        for (int i = 0; i < 4; i++) {
            int idx = tid + i * 256;
            int r = idx >> 3;
            int tok = toks[r];
            load_tile_f4(smem, aB, x + ((tok >= 0) ? ((size_t)tok * DD + k0) : 0), tok >= 0, idx);
            int n = n0 + r;
            bool bv = (n < NI);
            size_t boff = bv ? ((size_t)n * KD + k0) : 0;
            load_tile_f4(smem, b1B, w1p + boff, bv, idx);
            load_tile_f4(smem, b3B, w3p + boff, bv, idx);
        }
        __syncthreads();
        if (wid == 0) {
            if (elect_one_pred()) {
                FENCE_PROXY_ASYNC_SHARED_CTA();
                uint64_t ad  = MAKE_SMEM_DESC(sb + aB);
                uint64_t b1d = MAKE_SMEM_DESC(sb + b1B);
                uint64_t b3d = MAKE_SMEM_DESC(sb + b3B);
                #pragma unroll
                for (int k = 0; k < 4; k++) {
                    bool acc = (c > 0) || (k > 0);
                    mma_tf32_ss(tmem,       ad + k*2, b1d + k*2, IDESC_TF32_M128_N128, acc);
                    mma_tf32_ss(tmem + 128, ad + k*2, b3d + k*2, IDESC_TF32_M128_N128, acc);
                }
                TCGEN05_COMMIT(sb + SM_MBAR + 8 * buf);
            }
        }
    }
    MBARRIER_WAIT_PARITY(sb + SM_MBAR,     1);
    MBARRIER_WAIT_PARITY(sb + SM_MBAR + 8, 1);
    TCGEN05_FENCE_AFTER();

    float* st = (float*)(smem + SM_B1);
    for (int cb = 0; cb < 128; cb += 32) {
        if (tid < 128) {
            uint32_t d1[32], d2[32];
            TCGEN05_LD_32X32B_X32(d1, tmem + cb);
            TCGEN05_LD_32X32B_X32(d2, tmem + 128 + cb);
            TCGEN05_WAIT_LD();
            #pragma unroll
            for (int j = 0; j < 32; j++) {
                float v1 = __uint_as_float(d1[j]);
                float v3 = __uint_as_float(d2[j]);
                st[tid * 33 + j] = silu_mul(v1, v3);
            }
        }
        __syncthreads();
        #pragma unroll
        for (int i = 0; i < 16; i++) {
            int l = tid + i * 256;
            int r = l >> 5, cc = l & 31;
            int p = m0 + r;
            int col = n0 + cb + cc;
            if (p < cnt && col < NI)
                g_H[(size_t)(rowBase + p) * KD + 1 + col] = st[r * 33 + cc];
        }
        __syncthreads();
    }
    if (wid == 0) TCGEN05_DEALLOC(tmem, 256);
#else
    // --------------- portable mma.sync tf32 fallback: 128x64 block tile ----------
    int n0 = blockIdx.x * 64;
    int* toks = (int*)(smem + SM_TOKS);
    if (tid < 128) {
        int p = m0 + tid;
        toks[tid] = (p < cnt) ? ((e < EE) ? g_bucket[e * TT + p] : p) : -1;
    }
    __syncthreads();

    const uint32_t* As  = (const uint32_t*)(smem + F_SM_A);
    const uint32_t* B1s = (const uint32_t*)(smem + F_SM_B1);
    const uint32_t* B3s = (const uint32_t*)(smem + F_SM_B3);
    int lane = tid & 31, grp = lane >> 2, tig = lane & 3;
    int wid = tid >> 5;
    int mbase = (wid & 3) * 32, nbase = (wid >> 2) * 32;

    float c1[2][4][4], c3[2][4][4];
    #pragma unroll
    for (int mt = 0; mt < 2; mt++)
        #pragma unroll
        for (int nt = 0; nt < 4; nt++)
            #pragma unroll
            for (int q = 0; q < 4; q++) { c1[mt][nt][q] = 0.f; c3[mt][nt][q] = 0.f; }

    for (int c = 0; c < 32; c++) {
        if (c) __syncthreads();
        int k0 = c * 32;
        // copy A (128 rows x 32): 4 float4 per thread
        #pragma unroll
        for (int i = 0; i < 4; i++) {
            int idx = tid + i * 256;
            int r = idx >> 3, c4 = idx & 7;
            int tok = toks[r];
            fb_store_tf32(smem, F_SM_A, r, c4,
                          x + ((tok >= 0) ? ((size_t)tok * DD + k0) : 0), tok >= 0);
        }
        // copy B1/B3 (64 rows x 32): 2 float4 per thread each
        #pragma unroll
        for (int i = 0; i < 2; i++) {
            int idx = tid + i * 256;
            int r = idx >> 3, c4 = idx & 7;
            int n = n0 + r;
            bool bv = (n < NI);
            size_t boff = bv ? ((size_t)n * KD + k0) : 0;
            fb_store_tf32(smem, F_SM_B1, r, c4, w1p + boff, bv);
            fb_store_tf32(smem, F_SM_B3, r, c4, w3p + boff, bv);
        }
        __syncthreads();
        #pragma unroll
        for (int ks = 0; ks < 4; ks++) {
            int kk = ks * 8;
            uint32_t a[2][4];
            #pragma unroll
            for (int mt = 0; mt < 2; mt++) {
                int r0 = mbase + mt * 16 + grp;
                a[mt][0] = As[r0 * F_ASTR + kk + tig];
                a[mt][1] = As[(r0 + 8) * F_ASTR + kk + tig];
                a[mt][2] = As[r0 * F_ASTR + kk + tig + 4];
                a[mt][3] = As[(r0 + 8) * F_ASTR + kk + tig + 4];
            }
            uint32_t b1[4][2], b3[4][2];
            #pragma unroll
            for (int nt = 0; nt < 4; nt++) {
                int cr = nbase + nt * 8 + grp;
                b1[nt][0] = B1s[cr * F_ASTR + kk + tig];
                b1[nt][1] = B1s[cr * F_ASTR + kk + tig + 4];
                b3[nt][0] = B3s[cr * F_ASTR + kk + tig];
                b3[nt][1] = B3s[cr * F_ASTR + kk + tig + 4];
            }
            #pragma unroll
            for (int mt = 0; mt < 2; mt++)
                #pragma unroll
                for (int nt = 0; nt < 4; nt++) {
                    MMA_TF32_SYNC(c1[mt][nt], a[mt], b1[nt]);
                    MMA_TF32_SYNC(c3[mt][nt], a[mt], b3[nt]);
                }
        }
    }
    // epilogue
    #pragma unroll
    for (int mt = 0; mt < 2; mt++) {
        int pr = mbase + mt * 16 + grp;
        #pragma unroll
        for (int nt = 0; nt < 4; nt++) {
            int col = n0 + nbase + nt * 8 + 2 * tig;
            int p = m0 + pr;
            if (p < cnt) {
                float* hrow = g_H + (size_t)(rowBase + p) * KD + 1;
                if (col < NI)     hrow[col]     = silu_mul(c1[mt][nt][0], c3[mt][nt][0]);
                if (col + 1 < NI) hrow[col + 1] = silu_mul(c1[mt][nt][1], c3[mt][nt][1]);
            }
            int p2 = p + 8;
            if (p2 < cnt) {
                float* hrow = g_H + (size_t)(rowBase + p2) * KD + 1;
                if (col < NI)     hrow[col]     = silu_mul(c1[mt][nt][2], c3[mt][nt][2]);
                if (col + 1 < NI) hrow[col + 1] = silu_mul(c1[mt][nt][3], c3[mt][nt][3]);
            }
        }
    }
#endif
}

// ------------------------------ GEMM 2 ------------------------------------------
__global__ __launch_bounds__(256) void gemm2_tc(
    const float* __restrict__ W2, const float* __restrict__ Ws2)
{
    extern __shared__ char smem[];
    int tid = threadIdx.x;

    int e = blockIdx.z;
    int cnt; const float* wp; int rowBase;
    if (e < EE) { cnt = g_cnt[e]; wp = W2 + (size_t)e * NI * KD; rowBase = e * TT; }
    else        { cnt = TT;       wp = Ws2;                      rowBase = SHARED_BASE; }
    int m0 = blockIdx.y * 128;
    if (m0 >= cnt) return;

#if HAS_TCGEN05
    if (blockIdx.x & 1) return;
    int n0 = (blockIdx.x >> 1) * 128;
    uint32_t sb = smem_to_u32(smem);
    int wid = tid >> 5;

    if (wid == 0) TCGEN05_ALLOC(sb + SM_TMEM, 128);
    if (tid == 0) { MBARRIER_INIT(sb + SM_MBAR, 1); MBARRIER_INIT(sb + SM_MBAR + 8, 1); }
    __syncthreads();
    uint32_t tmem;
    asm volatile("ld.shared.b32 %0, [%1];" : "=r"(tmem) : "r"(sb + SM_TMEM));

    for (int c = 0; c < NCHUNK; c++) {
        int buf = c & 1;
        if (c >= 2) MBARRIER_WAIT_PARITY(sb + SM_MBAR + 8 * buf, ((c >> 1) - 1) & 1);
        int k0 = c * 32;
        uint32_t aB = SM_A  + buf * TILEB;
        uint32_t bB = SM_B1 + buf * TILEB;
        #pragma unroll
        for (int i = 0; i < 4; i++) {
            int idx = tid + i * 256;
            int r = idx >> 3;
            int p = m0 + r;
            bool av = (p < cnt);
            load_tile_f4(smem, aB, g_H + (av ? ((size_t)(rowBase + p) * KD + k0) : 0), av, idx);
            int n = n0 + r;
            bool bv = (n < NI);
            load_tile_f4(smem, bB, wp + (bv ? ((size_t)n * KD + k0) : 0), bv, idx);
        }
        __syncthreads();
        if (wid == 0) {
            if (elect_one_pred()) {
                FENCE_PROXY_ASYNC_SHARED_CTA();
                uint64_t ad = MAKE_SMEM_DESC(sb + aB);
                uint64_t bd = MAKE_SMEM_DESC(sb + bB);
                #pragma unroll
                for (int k = 0; k < 4; k++) {
                    bool acc = (c > 0) || (k > 0);
                    mma_tf32_ss(tmem, ad + k*2, bd + k*2, IDESC_TF32_M128_N128, acc);
                }
                TCGEN05_COMMIT(sb + SM_MBAR + 8 * buf);
            }
        }
    }
    MBARRIER_WAIT_PARITY(sb + SM_MBAR,     1);
    MBARRIER_WAIT_PARITY(sb + SM_MBAR + 8, 1);
    TCGEN05_FENCE_AFTER();

    float* st = (float*)(smem + SM_B1);
    for (int cb = 0; cb < 128; cb += 32) {
        if (tid < 128) {
            uint32_t d[32];
            TCGEN05_LD_32X32B_X32(d, tmem + cb);
            TCGEN05_WAIT_LD();
            #pragma unroll
            for (int j = 0; j < 32; j++) st[tid * 33 + j] = __uint_as_float(d[j]);
        }
        __syncthreads();
        #pragma unroll
        for (int i = 0; i < 16; i++) {
            int l = tid + i * 256;
            int r = l >> 5, cc = l & 31;
            int p = m0 + r;
            int col = n0 + cb + cc;
            if (p < cnt && col < NI)
                g_O[(size_t)(rowBase + p) * KD + 1 + col] = st[r * 33 + cc];
        }
        __syncthreads();
    }
    if (wid == 0) TCGEN05_DEALLOC(tmem, 128);
#else
    // --------------- portable mma.sync tf32 fallback ------------------------------
    int n0 = blockIdx.x * 64;
    const uint32_t* As = (const uint32_t*)(smem + F_SM_A);
    const uint32_t* Bs = (const uint32_t*)(smem + F_SM_B1);
    int lane = tid & 31, grp = lane >> 2, tig = lane & 3;
    int wid = tid >> 5;
    int mbase = (wid & 3) * 32, nbase = (wid >> 2) * 32;

    float acc[2][4][4];
    #pragma unroll
    for (int mt = 0; mt < 2; mt++)
        #pragma unroll
        for (int nt = 0; nt < 4; nt++)
            #pragma unroll
            for (int q = 0; q < 4; q++) acc[mt][nt][q] = 0.f;

    for (int c = 0; c < 32; c++) {
        if (c) __syncthreads();
        int k0 = c * 32;
        #pragma unroll
        for (int i = 0; i < 4; i++) {
            int idx = tid + i * 256;
            int r = idx >> 3, c4 = idx & 7;
            int p = m0 + r;
            bool av = (p < cnt);
            fb_store_tf32(smem, F_SM_A, r, c4,
                          g_H + (av ? ((size_t)(rowBase + p) * KD + k0) : 0), av);
        }
        #pragma unroll
        for (int i = 0; i < 2; i++) {
            int idx = tid + i * 256;
            int r = idx >> 3, c4 = idx & 7;
            int n = n0 + r;
            bool bv = (n < NI);
            fb_store_tf32(smem, F_SM_B1, r, c4, wp + (bv ? ((size_t)n * KD + k0) : 0), bv);
        }
        __syncthreads();
        #pragma unroll
        for (int ks = 0; ks < 4; ks++) {
            int kk = ks * 8;
            uint32_t a[2][4];
            #pragma unroll
            for (int mt = 0; mt < 2; mt++) {
                int r0 = mbase + mt * 16 + grp;
                a[mt][0] = As[r0 * F_ASTR + kk + tig];
                a[mt][1] = As[(r0 + 8) * F_ASTR + kk + tig];
                a[mt][2] = As[r0 * F_ASTR + kk + tig + 4];
                a[mt][3] = As[(r0 + 8) * F_ASTR + kk + tig + 4];
            }
            #pragma unroll
            for (int nt = 0; nt < 4; nt++) {
                int cr = nbase + nt * 8 + grp;
                uint32_t b[2];
                b[0] = Bs[cr * F_ASTR + kk + tig];
                b[1] = Bs[cr * F_ASTR + kk + tig + 4];
                #pragma unroll
                for (int mt = 0; mt < 2; mt++)
                    MMA_TF32_SYNC(acc[mt][nt], a[mt], b);
            }
        }
    }
    #pragma unroll
    for (int mt = 0; mt < 2; mt++) {
        int pr = mbase + mt * 16 + grp;
        #pragma unroll
        for (int nt = 0; nt < 4; nt++) {
            int col = n0 + nbase + nt * 8 + 2 * tig;
            int p = m0 + pr;
            if (p < cnt) {
                float* orow = g_O + (size_t)(rowBase + p) * KD + 1;
                if (col < NI)     orow[col]     = acc[mt][nt][0];
                if (col + 1 < NI) orow[col + 1] = acc[mt][nt][1];
            }
            int p2 = p + 8;
            if (p2 < cnt) {
                float* orow = g_O + (size_t)(rowBase + p2) * KD + 1;
                if (col < NI)     orow[col]     = acc[mt][nt][2];
                if (col + 1 < NI) orow[col + 1] = acc[mt][nt][3];
            }
        }
    }
#endif
}

// ------------------------------- launcher --------------------------------------
extern "C" void kernel_launch(void* const* d_in, const int* in_sizes, int n_in,
                              void* d_out, int out_size) {
    const float* x      = (const float*)d_in[0];
    const float* gate_w = (const float*)d_in[1];
    const float* gate_b = (const float*)d_in[2];
    const float* W1     = (const float*)d_in[3];
    const float* W3     = (const float*)d_in[4];
    const float* W2     = (const float*)d_in[5];
    const float* Ws1    = (const float*)d_in[6];
    const float* Ws3    = (const float*)d_in[7];
    const float* Ws2    = (const float*)d_in[8];
    float* out = (float*)d_out;

    cudaFuncSetAttribute(gemm1_tc, cudaFuncAttributeMaxDynamicSharedMemorySize, SMEM1_TOTAL);
    cudaFuncSetAttribute(gemm2_tc, cudaFuncAttributeMaxDynamicSharedMemorySize, SMEM2_TOTAL);

    zero_cnt_kernel<<<1, 32>>>();
    gate_kernel<<<TT, 256>>>(x, gate_w, gate_b);
    gemm1_tc<<<dim3(16, 16, 9), 256, SMEM1_TOTAL>>>(x, W1, W3, Ws1, Ws3);
    norm_kernel<<<2 * TT, 256>>>(0);
    gemm2_tc<<<dim3(16, 16, 9), 256, SMEM2_TOTAL>>>(W2, Ws2);
    norm_kernel<<<2 * TT, 256>>>(1);
    combine_kernel<<<TT, 256>>>(out);
}

// round 4
// speedup vs baseline: 3.1783x; 1.0786x over previous
#include <cuda_runtime.h>
#include <math.h>
#include <stdint.h>

// Problem constants (fixed by the reference setup_inputs)
#define TT 2048      // tokens
#define DD 1024      // model dim (Lorentz, incl. time coord)
#define EE 8         // experts
#define NI 1023      // I-1 == D-1 (space dims)
#define KD 1024      // GEMM K dim (= D = I)

#define ROWS_ROUTED (EE * TT)
#define SHARED_BASE ROWS_ROUTED
#define TOTAL_ROWS  (ROWS_ROUTED + TT)

// ------------------- device scratch (no allocations allowed) -------------------
__device__ float g_H[(size_t)TOTAL_ROWS * KD];
__device__ float g_O[(size_t)TOTAL_ROWS * KD];
__device__ int   g_cnt[EE];
__device__ int   g_bucket[ROWS_ROUTED];
__device__ int   g_rowOf[TT];
__device__ float g_wgt[TT];

// ------------------------------ helpers -----------------------------------------
__device__ __forceinline__ uint32_t smem_to_u32(const void* p) {
    uint32_t a;
    asm("{ .reg .u64 t; cvta.to.shared.u64 t, %1; cvt.u32.u64 %0, t; }" : "=r"(a) : "l"(p));
    return a;
}
__device__ __forceinline__ uint32_t f2tf32(float f) {
    uint32_t o; asm("cvt.rna.tf32.f32 %0, %1;" : "=r"(o) : "f"(f)); return o;
}
__device__ __forceinline__ float silu_mul(float v1, float v3) {
    return v1 * v3 / (1.0f + expf(-v1));
}

// cp.async 16B with zero-fill when src_size == 0
__device__ __forceinline__ void cp_async16(uint32_t smem_addr, const void* gptr, uint32_t src_size) {
    asm volatile("cp.async.cg.shared.global [%0], [%1], 16, %2;"
                 :: "r"(smem_addr), "l"(gptr), "r"(src_size) : "memory");
}
#define CP_COMMIT() asm volatile("cp.async.commit_group;" ::: "memory")
#define CP_WAIT1()  asm volatile("cp.async.wait_group 1;" ::: "memory")

// Portable tf32 mma.sync (sm_80+)
#define MMA_TF32_SYNC(d, a, b) \
    asm volatile("mma.sync.aligned.m16n8k8.row.col.f32.tf32.tf32.f32 " \
        "{%0,%1,%2,%3}, {%4,%5,%6,%7}, {%8,%9}, {%0,%1,%2,%3};" \
        : "+f"((d)[0]), "+f"((d)[1]), "+f"((d)[2]), "+f"((d)[3]) \
        : "r"((a)[0]), "r"((a)[1]), "r"((a)[2]), "r"((a)[3]), \
          "r"((b)[0]), "r"((b)[1]))

// ------------------------------- small kernels ----------------------------------
__device__ __forceinline__ float block_reduce_sum(float v) {
    __shared__ float red[32];
    int lane = threadIdx.x & 31, w = threadIdx.x >> 5;
    #pragma unroll
    for (int o = 16; o; o >>= 1) v += __shfl_down_sync(0xffffffffu, v, o);
    if (lane == 0) red[w] = v;
    __syncthreads();
    int nw = (blockDim.x + 31) >> 5;
    v = (threadIdx.x < nw) ? red[threadIdx.x] : 0.0f;
    if (w == 0) {
        #pragma unroll
        for (int o = 16; o; o >>= 1) v += __shfl_down_sync(0xffffffffu, v, o);
        if (lane == 0) red[0] = v;
    }
    __syncthreads();
    return red[0];
}

__global__ void zero_cnt_kernel() {
    if (threadIdx.x < EE) g_cnt[threadIdx.x] = 0;
}

__global__ void gate_kernel(const float* __restrict__ x,
                            const float* __restrict__ gate_w,
                            const float* __restrict__ gate_b) {
    int t = blockIdx.x;
    int tid = threadIdx.x;
    int w = tid >> 5, lane = tid & 31;
    __shared__ float s_logit[EE];
    const float* xr = x + (size_t)t * DD + 1;
    const float* gr = gate_w + (size_t)w * NI;
    float s = 0.0f;
    for (int j = lane; j < NI; j += 32) s += xr[j] * gr[j];
    #pragma unroll
    for (int o = 16; o; o >>= 1) s += __shfl_down_sync(0xffffffffu, s, o);
    if (lane == 0) s_logit[w] = s;
    __syncthreads();
    if (tid == 0) {
        float m = s_logit[0];
        #pragma unroll
        for (int e = 1; e < EE; e++) m = fmaxf(m, s_logit[e]);
        float ex[EE], den = 0.0f;
        #pragma unroll
        for (int e = 0; e < EE; e++) { ex[e] = expf(s_logit[e] - m); den += ex[e]; }
        float inv = 1.0f / den;
        float best = -1e30f; int bi = 0;
        #pragma unroll
        for (int e = 0; e < EE; e++) {
            float biased = ex[e] * inv + gate_b[e];
            if (biased > best) { best = biased; bi = e; }
        }
        g_wgt[t] = ex[bi] * inv;
        int p = atomicAdd(&g_cnt[bi], 1);
        g_bucket[bi * TT + p] = t;
        g_rowOf[t] = bi * TT + p;
    }
}

__global__ void norm_kernel(int which) {
    int b = blockIdx.x;
    int row = (b < TT) ? g_rowOf[b] : (SHARED_BASE + (b - TT));
    float* base = which ? g_O : g_H;
    float* r = base + (size_t)row * KD;
    float s = 0.0f;
    for (int c = 1 + threadIdx.x; c < KD; c += blockDim.x) {
        float v = r[c]; s += v * v;
    }
    float tot = block_reduce_sum(s);
    if (threadIdx.x == 0) r[0] = sqrtf(tot + 1.0f);
}

__global__ void combine_kernel(float* __restrict__ out) {
    int t = blockIdx.x;
    int tid = threadIdx.x;
    int rr = g_rowOf[t];
    float wgt = g_wgt[t];
    const float* zr = g_O + (size_t)(SHARED_BASE + t) * KD;
    const float* er = g_O + (size_t)rr * KD;
    float comb[4];
    float ss = 0.0f;
    #pragma unroll
    for (int i = 0; i < 4; i++) {
        int d = tid + i * 256;
        float y = (d == 0) ? (1.0f + wgt * er[0]) : (wgt * er[d]);
        float c = zr[d] + 2.0f * y;
        comb[i] = c;
        if (d != 0) ss += c * c;
    }
    float space_sq = block_reduce_sum(ss);
    float comb0 = zr[0] + 2.0f * (1.0f + wgt * er[0]);
    float li = space_sq - comb0 * comb0;
    float scale = rsqrtf(fmaxf(fabsf(li), 1e-8f));
    #pragma unroll
    for (int i = 0; i < 4; i++) {
        int d = tid + i * 256;
        out[(size_t)t * DD + d] = comb[i] * scale;
    }
}

// ------------------------- pipelined tf32 mma.sync GEMMs ------------------------
// Block tile: 128 (M) x 64 (N), K-chunks of 32, 3-stage cp.async pipeline.
// 8 warps, each computing a 32x32 warp tile (2x4 grid of m16n8k8 mma).
#define ASTR   36                        // padded row stride (floats) for A and B tiles
#define A_BYTES (128 * ASTR * 4)         // 18432
#define B_BYTES (64  * ASTR * 4)         // 9216
#define STAGES 3
#define NCHUNK 32

// gemm1 stage layout: [A | B1 | B3]
#define S1_STAGE (A_BYTES + 2 * B_BYTES)            // 36864
#define SMEM1_TOTAL (1024 + STAGES * S1_STAGE)      // 111616
// gemm2 stage layout: [A | B]
#define S2_STAGE (A_BYTES + B_BYTES)                // 27648
#define SMEM2_TOTAL (1024 + STAGES * S2_STAGE)      // 83968

// ------------------------------ GEMM 1 ------------------------------------------
__global__ __launch_bounds__(256) void gemm1_tc(
    const float* __restrict__ x,
    const float* __restrict__ W1, const float* __restrict__ W3,
    const float* __restrict__ Ws1, const float* __restrict__ Ws3)
{
    extern __shared__ char smem[];
    int tid = threadIdx.x;

    int e = blockIdx.z;
    int cnt; const float *w1p, *w3p; int rowBase;
    if (e < EE) {
        cnt = g_cnt[e];
        w1p = W1 + (size_t)e * NI * KD;
        w3p = W3 + (size_t)e * NI * KD;
        rowBase = e * TT;
    } else {
        cnt = TT; w1p = Ws1; w3p = Ws3; rowBase = SHARED_BASE;
    }
    int m0 = blockIdx.y * 128;
    if (m0 >= cnt) return;
    int n0 = blockIdx.x * 64;

    int* toks = (int*)smem;                     // first 512B
    uint32_t sb = smem_to_u32(smem);
    uint32_t sbuf = sb + 1024;

    if (tid < 128) {
        int p = m0 + tid;
        toks[tid] = (p < cnt) ? ((e < EE) ? g_bucket[e * TT + p] : p) : -1;
    }
    __syncthreads();

    // per-thread load assignments (same every chunk)
    // A: idx = tid + i*256, i<4  -> row r = idx>>3 (0..127), chunk c4 = idx&7
    // B: idx = tid + i*256, i<2  -> row r (0..63), c4
    int a_r[4], a_c4[4], a_tok[4];
    #pragma unroll
    for (int i = 0; i < 4; i++) {
        int idx = tid + i * 256;
        a_r[i] = idx >> 3; a_c4[i] = idx & 7;
        a_tok[i] = toks[a_r[i]];
    }
    int b_r[2], b_c4[2];
    #pragma unroll
    for (int i = 0; i < 2; i++) {
        int idx = tid + i * 256;
        b_r[i] = idx >> 3; b_c4[i] = idx & 7;
    }

    auto issue_stage = [&](int c) {
        int buf = c % STAGES;
        uint32_t aB  = sbuf + buf * S1_STAGE;
        uint32_t b1B = aB + A_BYTES;
        uint32_t b3B = b1B + B_BYTES;
        int k0 = c * 32;
        #pragma unroll
        for (int i = 0; i < 4; i++) {
            int tok = a_tok[i];
            const float* src = x + ((tok >= 0) ? ((size_t)tok * DD + k0 + a_c4[i] * 4) : 0);
            cp_async16(aB + (a_r[i] * ASTR + a_c4[i] * 4) * 4, src, (tok >= 0) ? 16u : 0u);
        }
        #pragma unroll
        for (int i = 0; i < 2; i++) {
            int n = n0 + b_r[i];
            bool bv = (n < NI);
            size_t off = bv ? ((size_t)n * KD + k0 + b_c4[i] * 4) : 0;
            uint32_t so = (b_r[i] * ASTR + b_c4[i] * 4) * 4;
            cp_async16(b1B + so, w1p + off, bv ? 16u : 0u);
            cp_async16(b3B + so, w3p + off, bv ? 16u : 0u);
        }
        CP_COMMIT();
    };

    int lane = tid & 31, grp = lane >> 2, tig = lane & 3;
    int wid = tid >> 5;
    int mbase = (wid & 3) * 32, nbase = (wid >> 2) * 32;

    float c1[2][4][4], c3[2][4][4];
    #pragma unroll
    for (int mt = 0; mt < 2; mt++)
        #pragma unroll
        for (int nt = 0; nt < 4; nt++)
            #pragma unroll
            for (int q = 0; q < 4; q++) { c1[mt][nt][q] = 0.f; c3[mt][nt][q] = 0.f; }

    issue_stage(0);
    issue_stage(1);

    for (int c = 0; c < NCHUNK; c++) {
        CP_WAIT1();
        __syncthreads();
        if (c + STAGES - 1 < NCHUNK) issue_stage(c + STAGES - 1);
        else CP_COMMIT();

        int buf = c % STAGES;
        const float* As  = (const float*)(smem + 1024 + buf * S1_STAGE);
        const float* B1s = As + 128 * ASTR;
        const float* B3s = B1s + 64 * ASTR;

        #pragma unroll
        for (int ks = 0; ks < 4; ks++) {
            int kk = ks * 8;
            uint32_t a[2][4];
            #pragma unroll
            for (int mt = 0; mt < 2; mt++) {
                int r0 = mbase + mt * 16 + grp;
                a[mt][0] = f2tf32(As[r0 * ASTR + kk + tig]);
                a[mt][1] = f2tf32(As[(r0 + 8) * ASTR + kk + tig]);
                a[mt][2] = f2tf32(As[r0 * ASTR + kk + tig + 4]);
                a[mt][3] = f2tf32(As[(r0 + 8) * ASTR + kk + tig + 4]);
            }
            uint32_t b1[4][2], b3[4][2];
            #pragma unroll
            for (int nt = 0; nt < 4; nt++) {
                int cr = nbase + nt * 8 + grp;
                b1[nt][0] = f2tf32(B1s[cr * ASTR + kk + tig]);
                b1[nt][1] = f2tf32(B1s[cr * ASTR + kk + tig + 4]);
                b3[nt][0] = f2tf32(B3s[cr * ASTR + kk + tig]);
                b3[nt][1] = f2tf32(B3s[cr * ASTR + kk + tig + 4]);
            }
            #pragma unroll
            for (int mt = 0; mt < 2; mt++)
                #pragma unroll
                for (int nt = 0; nt < 4; nt++) {
                    MMA_TF32_SYNC(c1[mt][nt], a[mt], b1[nt]);
                    MMA_TF32_SYNC(c3[mt][nt], a[mt], b3[nt]);
                }
        }
        __syncthreads();
    }

    // epilogue
    #pragma unroll
    for (int mt = 0; mt < 2; mt++) {
        int pr = mbase + mt * 16 + grp;
        #pragma unroll
        for (int nt = 0; nt < 4; nt++) {
            int col = n0 + nbase + nt * 8 + 2 * tig;
            int p = m0 + pr;
            if (p < cnt) {
                float* hrow = g_H + (size_t)(rowBase + p) * KD + 1;
                if (col < NI)     hrow[col]     = silu_mul(c1[mt][nt][0], c3[mt][nt][0]);
                if (col + 1 < NI) hrow[col + 1] = silu_mul(c1[mt][nt][1], c3[mt][nt][1]);
            }
            int p2 = p + 8;
            if (p2 < cnt) {
                float* hrow = g_H + (size_t)(rowBase + p2) * KD + 1;
                if (col < NI)     hrow[col]     = silu_mul(c1[mt][nt][2], c3[mt][nt][2]);
                if (col + 1 < NI) hrow[col + 1] = silu_mul(c1[mt][nt][3], c3[mt][nt][3]);
            }
        }
    }
}

// ------------------------------ GEMM 2 ------------------------------------------
__global__ __launch_bounds__(256) void gemm2_tc(
    const float* __restrict__ W2, const float* __restrict__ Ws2)
{
    extern __shared__ char smem[];
    int tid = threadIdx.x;

    int e = blockIdx.z;
    int cnt; const float* wp; int rowBase;
    if (e < EE) { cnt = g_cnt[e]; wp = W2 + (size_t)e * NI * KD; rowBase = e * TT; }
    else        { cnt = TT;       wp = Ws2;                      rowBase = SHARED_BASE; }
    int m0 = blockIdx.y * 128;
    if (m0 >= cnt) return;
    int n0 = blockIdx.x * 64;

    uint32_t sb = smem_to_u32(smem);
    uint32_t sbuf = sb + 1024;

    int a_r[4], a_c4[4];
    bool a_v[4];
    const float* a_src[4];
    #pragma unroll
    for (int i = 0; i < 4; i++) {
        int idx = tid + i * 256;
        a_r[i] = idx >> 3; a_c4[i] = idx & 7;
        int p = m0 + a_r[i];
        a_v[i] = (p < cnt);
        a_src[i] = g_H + (a_v[i] ? ((size_t)(rowBase + p) * KD + a_c4[i] * 4) : 0);
    }
    int b_r[2], b_c4[2];
    #pragma unroll
    for (int i = 0; i < 2; i++) {
        int idx = tid + i * 256;
        b_r[i] = idx >> 3; b_c4[i] = idx & 7;
    }

    auto issue_stage = [&](int c) {
        int buf = c % STAGES;
        uint32_t aB = sbuf + buf * S2_STAGE;
        uint32_t bB = aB + A_BYTES;
        int k0 = c * 32;
        #pragma unroll
        for (int i = 0; i < 4; i++)
            cp_async16(aB + (a_r[i] * ASTR + a_c4[i] * 4) * 4, a_src[i] + k0, a_v[i] ? 16u : 0u);
        #pragma unroll
        for (int i = 0; i < 2; i++) {
            int n = n0 + b_r[i];
            bool bv = (n < NI);
            size_t off = bv ? ((size_t)n * KD + k0 + b_c4[i] * 4) : 0;
            cp_async16(bB + (b_r[i] * ASTR + b_c4[i] * 4) * 4, wp + off, bv ? 16u : 0u);
        }
        CP_COMMIT();
    };

    int lane = tid & 31, grp = lane >> 2, tig = lane & 3;
    int wid = tid >> 5;
    int mbase = (wid & 3) * 32, nbase = (wid >> 2) * 32;

    float acc[2][4][4];
    #pragma unroll
    for (int mt = 0; mt < 2; mt++)
        #pragma unroll
        for (int nt = 0; nt < 4; nt++)
            #pragma unroll
            for (int q = 0; q < 4; q++) acc[mt][nt][q] = 0.f;

    issue_stage(0);
    issue_stage(1);

    for (int c = 0; c < NCHUNK; c++) {
        CP_WAIT1();
        __syncthreads();
        if (c + STAGES - 1 < NCHUNK) issue_stage(c + STAGES - 1);
        else CP_COMMIT();

        int buf = c % STAGES;
        const float* As = (const float*)(smem + 1024 + buf * S2_STAGE);
        const float* Bs = As + 128 * ASTR;

        #pragma unroll
        for (int ks = 0; ks < 4; ks++) {
            int kk = ks * 8;
            uint32_t a[2][4];
            #pragma unroll
            for (int mt = 0; mt < 2; mt++) {
                int r0 = mbase + mt * 16 + grp;
                a[mt][0] = f2tf32(As[r0 * ASTR + kk + tig]);
                a[mt][1] = f2tf32(As[(r0 + 8) * ASTR + kk + tig]);
                a[mt][2] = f2tf32(As[r0 * ASTR + kk + tig + 4]);
                a[mt][3] = f2tf32(As[(r0 + 8) * ASTR + kk + tig + 4]);
            }
            #pragma unroll
            for (int nt = 0; nt < 4; nt++) {
                int cr = nbase + nt * 8 + grp;
                uint32_t b[2];
                b[0] = f2tf32(Bs[cr * ASTR + kk + tig]);
                b[1] = f2tf32(Bs[cr * ASTR + kk + tig + 4]);
                #pragma unroll
                for (int mt = 0; mt < 2; mt++)
                    MMA_TF32_SYNC(acc[mt][nt], a[mt], b);
            }
        }
        __syncthreads();
    }

    #pragma unroll
    for (int mt = 0; mt < 2; mt++) {
        int pr = mbase + mt * 16 + grp;
        #pragma unroll
        for (int nt = 0; nt < 4; nt++) {
            int col = n0 + nbase + nt * 8 + 2 * tig;
            int p = m0 + pr;
            if (p < cnt) {
                float* orow = g_O + (size_t)(rowBase + p) * KD + 1;
                if (col < NI)     orow[col]     = acc[mt][nt][0];
                if (col + 1 < NI) orow[col + 1] = acc[mt][nt][1];
            }
            int p2 = p + 8;
            if (p2 < cnt) {
                float* orow = g_O + (size_t)(rowBase + p2) * KD + 1;
                if (col < NI)     orow[col]     = acc[mt][nt][2];
                if (col + 1 < NI) orow[col + 1] = acc[mt][nt][3];
            }
        }
    }
}

// ------------------------------- launcher --------------------------------------
extern "C" void kernel_launch(void* const* d_in, const int* in_sizes, int n_in,
                              void* d_out, int out_size) {
    const float* x      = (const float*)d_in[0];
    const float* gate_w = (const float*)d_in[1];
    const float* gate_b = (const float*)d_in[2];
    const float* W1     = (const float*)d_in[3];
    const float* W3     = (const float*)d_in[4];
    const float* W2     = (const float*)d_in[5];
    const float* Ws1    = (const float*)d_in[6];
    const float* Ws3    = (const float*)d_in[7];
    const float* Ws2    = (const float*)d_in[8];
    float* out = (float*)d_out;

    cudaFuncSetAttribute(gemm1_tc, cudaFuncAttributeMaxDynamicSharedMemorySize, SMEM1_TOTAL);
    cudaFuncSetAttribute(gemm2_tc, cudaFuncAttributeMaxDynamicSharedMemorySize, SMEM2_TOTAL);

    zero_cnt_kernel<<<1, 32>>>();
    gate_kernel<<<TT, 256>>>(x, gate_w, gate_b);
    gemm1_tc<<<dim3(16, 16, 9), 256, SMEM1_TOTAL>>>(x, W1, W3, Ws1, Ws3);
    norm_kernel<<<2 * TT, 256>>>(0);
    gemm2_tc<<<dim3(16, 16, 9), 256, SMEM2_TOTAL>>>(W2, Ws2);
    norm_kernel<<<2 * TT, 256>>>(1);
    combine_kernel<<<TT, 256>>>(out);
}

// round 5
// speedup vs baseline: 3.3444x; 1.0523x over previous
#include <cuda_runtime.h>
#include <math.h>
#include <stdint.h>

// Problem constants (fixed by the reference setup_inputs)
#define TT 2048      // tokens
#define DD 1024      // model dim (Lorentz, incl. time coord)
#define EE 8         // experts
#define NI 1023      // I-1 == D-1 (space dims)
#define KD 1024      // GEMM K dim (= D = I)

#define ROWS_ROUTED (EE * TT)
#define SHARED_BASE ROWS_ROUTED
#define TOTAL_ROWS  (ROWS_ROUTED + TT)

// ------------------- device scratch (no allocations allowed) -------------------
__device__ float g_H[(size_t)TOTAL_ROWS * KD];
__device__ float g_O[(size_t)TOTAL_ROWS * KD];
__device__ int   g_cnt[EE];
__device__ int   g_bucket[ROWS_ROUTED];
__device__ int   g_rowOf[TT];
__device__ float g_wgt[TT];

// ------------------------------ helpers -----------------------------------------
__device__ __forceinline__ uint32_t f2tf32(float f) {
    uint32_t o; asm("cvt.rna.tf32.f32 %0, %1;" : "=r"(o) : "f"(f)); return o;
}
__device__ __forceinline__ float silu_mul(float v1, float v3) {
    return v1 * v3 / (1.0f + __expf(-v1));
}

// cp.async 16B with zero-fill when src_size == 0
__device__ __forceinline__ void cp_async16(uint32_t smem_addr, const void* gptr, uint32_t src_size) {
    asm volatile("cp.async.cg.shared.global [%0], [%1], 16, %2;"
                 :: "r"(smem_addr), "l"(gptr), "r"(src_size) : "memory");
}
#define CP_COMMIT() asm volatile("cp.async.commit_group;" ::: "memory")
#define CP_WAIT1()  asm volatile("cp.async.wait_group 1;" ::: "memory")

__device__ __forceinline__ uint32_t smem_to_u32(const void* p) {
    uint32_t a;
    asm("{ .reg .u64 t; cvta.to.shared.u64 t, %1; cvt.u32.u64 %0, t; }" : "=r"(a) : "l"(p));
    return a;
}

// Portable tf32 mma.sync (sm_80+)
#define MMA_TF32_SYNC(d, a, b) \
    asm volatile("mma.sync.aligned.m16n8k8.row.col.f32.tf32.tf32.f32 " \
        "{%0,%1,%2,%3}, {%4,%5,%6,%7}, {%8,%9}, {%0,%1,%2,%3};" \
        : "+f"((d)[0]), "+f"((d)[1]), "+f"((d)[2]), "+f"((d)[3]) \
        : "r"((a)[0]), "r"((a)[1]), "r"((a)[2]), "r"((a)[3]), \
          "r"((b)[0]), "r"((b)[1]))

// ------------------------------- small kernels ----------------------------------
__device__ __forceinline__ float block_reduce_sum(float v) {
    __shared__ float red[32];
    int lane = threadIdx.x & 31, w = threadIdx.x >> 5;
    #pragma unroll
    for (int o = 16; o; o >>= 1) v += __shfl_down_sync(0xffffffffu, v, o);
    if (lane == 0) red[w] = v;
    __syncthreads();
    int nw = (blockDim.x + 31) >> 5;
    v = (threadIdx.x < nw) ? red[threadIdx.x] : 0.0f;
    if (w == 0) {
        #pragma unroll
        for (int o = 16; o; o >>= 1) v += __shfl_down_sync(0xffffffffu, v, o);
        if (lane == 0) red[0] = v;
    }
    __syncthreads();
    return red[0];
}

__global__ void zero_cnt_kernel() {
    if (threadIdx.x < EE) g_cnt[threadIdx.x] = 0;
}

__global__ void dummy_kernel() {}   // spacing so ncu (-s 5) captures gemm1

__global__ void gate_kernel(const float* __restrict__ x,
                            const float* __restrict__ gate_w,
                            const float* __restrict__ gate_b) {
    int t = blockIdx.x;
    int tid = threadIdx.x;
    int w = tid >> 5, lane = tid & 31;
    __shared__ float s_logit[EE];
    const float* xr = x + (size_t)t * DD + 1;
    const float* gr = gate_w + (size_t)w * NI;
    float s = 0.0f;
    for (int j = lane; j < NI; j += 32) s += xr[j] * gr[j];
    #pragma unroll
    for (int o = 16; o; o >>= 1) s += __shfl_down_sync(0xffffffffu, s, o);
    if (lane == 0) s_logit[w] = s;
    __syncthreads();
    if (tid == 0) {
        float m = s_logit[0];
        #pragma unroll
        for (int e = 1; e < EE; e++) m = fmaxf(m, s_logit[e]);
        float ex[EE], den = 0.0f;
        #pragma unroll
        for (int e = 0; e < EE; e++) { ex[e] = expf(s_logit[e] - m); den += ex[e]; }
        float inv = 1.0f / den;
        float best = -1e30f; int bi = 0;
        #pragma unroll
        for (int e = 0; e < EE; e++) {
            float biased = ex[e] * inv + gate_b[e];
            if (biased > best) { best = biased; bi = e; }
        }
        g_wgt[t] = ex[bi] * inv;
        int p = atomicAdd(&g_cnt[bi], 1);
        g_bucket[bi * TT + p] = t;
        g_rowOf[t] = bi * TT + p;
    }
}

__global__ void norm_kernel(int which) {
    int b = blockIdx.x;
    int row = (b < TT) ? g_rowOf[b] : (SHARED_BASE + (b - TT));
    float* base = which ? g_O : g_H;
    float* r = base + (size_t)row * KD;
    float s = 0.0f;
    for (int c = 1 + threadIdx.x; c < KD; c += blockDim.x) {
        float v = r[c]; s += v * v;
    }
    float tot = block_reduce_sum(s);
    if (threadIdx.x == 0) r[0] = sqrtf(tot + 1.0f);
}

__global__ void combine_kernel(float* __restrict__ out) {
    int t = blockIdx.x;
    int tid = threadIdx.x;
    int rr = g_rowOf[t];
    float wgt = g_wgt[t];
    const float* zr = g_O + (size_t)(SHARED_BASE + t) * KD;
    const float* er = g_O + (size_t)rr * KD;
    float comb[4];
    float ss = 0.0f;
    #pragma unroll
    for (int i = 0; i < 4; i++) {
        int d = tid + i * 256;
        float y = (d == 0) ? (1.0f + wgt * er[0]) : (wgt * er[d]);
        float c = zr[d] + 2.0f * y;
        comb[i] = c;
        if (d != 0) ss += c * c;
    }
    float space_sq = block_reduce_sum(ss);
    float comb0 = zr[0] + 2.0f * (1.0f + wgt * er[0]);
    float li = space_sq - comb0 * comb0;
    float scale = rsqrtf(fmaxf(fabsf(li), 1e-8f));
    #pragma unroll
    for (int i = 0; i < 4; i++) {
        int d = tid + i * 256;
        out[(size_t)t * DD + d] = comb[i] * scale;
    }
}

// ------------------------- pipelined tf32 mma.sync GEMMs ------------------------
// Block tile: 128 (M) x 64 (N), K-chunks of 32, 3-stage cp.async pipeline.
// 8 warps, each computing a 32x32 warp tile (2x4 grid of m16n8k8 mma).
#define ASTR   36                        // padded row stride (floats)
#define A_BYTES (128 * ASTR * 4)         // 18432
#define B_BYTES (64  * ASTR * 4)         // 9216
#define STAGES 3
#define NCHUNK 32

#define S1_STAGE (A_BYTES + 2 * B_BYTES)            // 36864
#define SMEM1_TOTAL (1024 + STAGES * S1_STAGE)      // 111616  (2 CTAs/SM: 223232 <= 228KB)
#define S2_STAGE (A_BYTES + B_BYTES)                // 27648
#define SMEM2_TOTAL (1024 + STAGES * S2_STAGE)      // 83968

// ------------------------------ GEMM 1 ------------------------------------------
__global__ void __launch_bounds__(256, 2) gemm1_tc(
    const float* __restrict__ x,
    const float* __restrict__ W1, const float* __restrict__ W3,
    const float* __restrict__ Ws1, const float* __restrict__ Ws3)
{
    extern __shared__ char smem[];
    int tid = threadIdx.x;

    int e = blockIdx.z;
    int cnt; const float *w1p, *w3p; int rowBase;
    if (e < EE) {
        cnt = g_cnt[e];
        w1p = W1 + (size_t)e * NI * KD;
        w3p = W3 + (size_t)e * NI * KD;
        rowBase = e * TT;
    } else {
        cnt = TT; w1p = Ws1; w3p = Ws3; rowBase = SHARED_BASE;
    }
    int m0 = blockIdx.y * 128;
    if (m0 >= cnt) return;
    int n0 = blockIdx.x * 64;

    int* toks = (int*)smem;
    uint32_t sb = smem_to_u32(smem);
    uint32_t sbuf = sb + 1024;

    if (tid < 128) {
        int p = m0 + tid;
        toks[tid] = (p < cnt) ? ((e < EE) ? g_bucket[e * TT + p] : p) : -1;
    }
    __syncthreads();

    int a_r[4], a_c4[4], a_tok[4];
    #pragma unroll
    for (int i = 0; i < 4; i++) {
        int idx = tid + i * 256;
        a_r[i] = idx >> 3; a_c4[i] = idx & 7;
        a_tok[i] = toks[a_r[i]];
    }
    int b_r[2], b_c4[2];
    #pragma unroll
    for (int i = 0; i < 2; i++) {
        int idx = tid + i * 256;
        b_r[i] = idx >> 3; b_c4[i] = idx & 7;
    }

    auto issue_stage = [&](int c) {
        int buf = c % STAGES;
        uint32_t aB  = sbuf + buf * S1_STAGE;
        uint32_t b1B = aB + A_BYTES;
        uint32_t b3B = b1B + B_BYTES;
        int k0 = c * 32;
        #pragma unroll
        for (int i = 0; i < 4; i++) {
            int tok = a_tok[i];
            const float* src = x + ((tok >= 0) ? ((size_t)tok * DD + k0 + a_c4[i] * 4) : 0);
            cp_async16(aB + (a_r[i] * ASTR + a_c4[i] * 4) * 4, src, (tok >= 0) ? 16u : 0u);
        }
        #pragma unroll
        for (int i = 0; i < 2; i++) {
            int n = n0 + b_r[i];
            bool bv = (n < NI);
            size_t off = bv ? ((size_t)n * KD + k0 + b_c4[i] * 4) : 0;
            uint32_t so = (b_r[i] * ASTR + b_c4[i] * 4) * 4;
            cp_async16(b1B + so, w1p + off, bv ? 16u : 0u);
            cp_async16(b3B + so, w3p + off, bv ? 16u : 0u);
        }
        CP_COMMIT();
    };

    int lane = tid & 31, grp = lane >> 2, tig = lane & 3;
    int wid = tid >> 5;
    int mbase = (wid & 3) * 32, nbase = (wid >> 2) * 32;

    float c1[2][4][4], c3[2][4][4];
    #pragma unroll
    for (int mt = 0; mt < 2; mt++)
        #pragma unroll
        for (int nt = 0; nt < 4; nt++)
            #pragma unroll
            for (int q = 0; q < 4; q++) { c1[mt][nt][q] = 0.f; c3[mt][nt][q] = 0.f; }

    issue_stage(0);
    issue_stage(1);

    for (int c = 0; c < NCHUNK; c++) {
        CP_WAIT1();
        __syncthreads();
        if (c + STAGES - 1 < NCHUNK) issue_stage(c + STAGES - 1);
        else CP_COMMIT();

        int buf = c % STAGES;
        const float* As  = (const float*)(smem + 1024 + buf * S1_STAGE);
        const float* B1s = As + 128 * ASTR;
        const float* B3s = B1s + 64 * ASTR;

        #pragma unroll
        for (int ks = 0; ks < 4; ks++) {
            int kk = ks * 8;
            uint32_t a[2][4];
            #pragma unroll
            for (int mt = 0; mt < 2; mt++) {
                int r0 = mbase + mt * 16 + grp;
                a[mt][0] = f2tf32(As[r0 * ASTR + kk + tig]);
                a[mt][1] = f2tf32(As[(r0 + 8) * ASTR + kk + tig]);
                a[mt][2] = f2tf32(As[r0 * ASTR + kk + tig + 4]);
                a[mt][3] = f2tf32(As[(r0 + 8) * ASTR + kk + tig + 4]);
            }
            uint32_t b1[4][2], b3[4][2];
            #pragma unroll
            for (int nt = 0; nt < 4; nt++) {
                int cr = nbase + nt * 8 + grp;
                b1[nt][0] = f2tf32(B1s[cr * ASTR + kk + tig]);
                b1[nt][1] = f2tf32(B1s[cr * ASTR + kk + tig + 4]);
                b3[nt][0] = f2tf32(B3s[cr * ASTR + kk + tig]);
                b3[nt][1] = f2tf32(B3s[cr * ASTR + kk + tig + 4]);
            }
            #pragma unroll
            for (int mt = 0; mt < 2; mt++)
                #pragma unroll
                for (int nt = 0; nt < 4; nt++) {
                    MMA_TF32_SYNC(c1[mt][nt], a[mt], b1[nt]);
                    MMA_TF32_SYNC(c3[mt][nt], a[mt], b3[nt]);
                }
        }
        __syncthreads();
    }

    #pragma unroll
    for (int mt = 0; mt < 2; mt++) {
        int pr = mbase + mt * 16 + grp;
        #pragma unroll
        for (int nt = 0; nt < 4; nt++) {
            int col = n0 + nbase + nt * 8 + 2 * tig;
            int p = m0 + pr;
            if (p < cnt) {
                float* hrow = g_H + (size_t)(rowBase + p) * KD + 1;
                if (col < NI)     hrow[col]     = silu_mul(c1[mt][nt][0], c3[mt][nt][0]);
                if (col + 1 < NI) hrow[col + 1] = silu_mul(c1[mt][nt][1], c3[mt][nt][1]);
            }
            int p2 = p + 8;
            if (p2 < cnt) {
                float* hrow = g_H + (size_t)(rowBase + p2) * KD + 1;
                if (col < NI)     hrow[col]     = silu_mul(c1[mt][nt][2], c3[mt][nt][2]);
                if (col + 1 < NI) hrow[col + 1] = silu_mul(c1[mt][nt][3], c3[mt][nt][3]);
            }
        }
    }
}

// ------------------------------ GEMM 2 ------------------------------------------
__global__ void __launch_bounds__(256, 2) gemm2_tc(
    const float* __restrict__ W2, const float* __restrict__ Ws2)
{
    extern __shared__ char smem[];
    int tid = threadIdx.x;

    int e = blockIdx.z;
    int cnt; const float* wp; int rowBase;
    if (e < EE) { cnt = g_cnt[e]; wp = W2 + (size_t)e * NI * KD; rowBase = e * TT; }
    else        { cnt = TT;       wp = Ws2;                      rowBase = SHARED_BASE; }
    int m0 = blockIdx.y * 128;
    if (m0 >= cnt) return;
    int n0 = blockIdx.x * 64;

    uint32_t sb = smem_to_u32(smem);
    uint32_t sbuf = sb + 1024;

    int a_r[4], a_c4[4];
    bool a_v[4];
    const float* a_src[4];
    #pragma unroll
    for (int i = 0; i < 4; i++) {
        int idx = tid + i * 256;
        a_r[i] = idx >> 3; a_c4[i] = idx & 7;
        int p = m0 + a_r[i];
        a_v[i] = (p < cnt);
        a_src[i] = g_H + (a_v[i] ? ((size_t)(rowBase + p) * KD + a_c4[i] * 4) : 0);
    }
    int b_r[2], b_c4[2];
    #pragma unroll
    for (int i = 0; i < 2; i++) {
        int idx = tid + i * 256;
        b_r[i] = idx >> 3; b_c4[i] = idx & 7;
    }

    auto issue_stage = [&](int c) {
        int buf = c % STAGES;
        uint32_t aB = sbuf + buf * S2_STAGE;
        uint32_t bB = aB + A_BYTES;
        int k0 = c * 32;
        #pragma unroll
        for (int i = 0; i < 4; i++)
            cp_async16(aB + (a_r[i] * ASTR + a_c4[i] * 4) * 4, a_src[i] + k0, a_v[i] ? 16u : 0u);
        #pragma unroll
        for (int i = 0; i < 2; i++) {
            int n = n0 + b_r[i];
            bool bv = (n < NI);
            size_t off = bv ? ((size_t)n * KD + k0 + b_c4[i] * 4) : 0;
            cp_async16(bB + (b_r[i] * ASTR + b_c4[i] * 4) * 4, wp + off, bv ? 16u : 0u);
        }
        CP_COMMIT();
    };

    int lane = tid & 31, grp = lane >> 2, tig = lane & 3;
    int wid = tid >> 5;
    int mbase = (wid & 3) * 32, nbase = (wid >> 2) * 32;

    float acc[2][4][4];
    #pragma unroll
    for (int mt = 0; mt < 2; mt++)
        #pragma unroll
        for (int nt = 0; nt < 4; nt++)
            #pragma unroll
            for (int q = 0; q < 4; q++) acc[mt][nt][q] = 0.f;

    issue_stage(0);
    issue_stage(1);

    for (int c = 0; c < NCHUNK; c++) {
        CP_WAIT1();
        __syncthreads();
        if (c + STAGES - 1 < NCHUNK) issue_stage(c + STAGES - 1);
        else CP_COMMIT();

        int buf = c % STAGES;
        const float* As = (const float*)(smem + 1024 + buf * S2_STAGE);
        const float* Bs = As + 128 * ASTR;

        #pragma unroll
        for (int ks = 0; ks < 4; ks++) {
            int kk = ks * 8;
            uint32_t a[2][4];
            #pragma unroll
            for (int mt = 0; mt < 2; mt++) {
                int r0 = mbase + mt * 16 + grp;
                a[mt][0] = f2tf32(As[r0 * ASTR + kk + tig]);
                a[mt][1] = f2tf32(As[(r0 + 8) * ASTR + kk + tig]);
                a[mt][2] = f2tf32(As[r0 * ASTR + kk + tig + 4]);
                a[mt][3] = f2tf32(As[(r0 + 8) * ASTR + kk + tig + 4]);
            }
            #pragma unroll
            for (int nt = 0; nt < 4; nt++) {
                int cr = nbase + nt * 8 + grp;
                uint32_t b[2];
                b[0] = f2tf32(Bs[cr * ASTR + kk + tig]);
                b[1] = f2tf32(Bs[cr * ASTR + kk + tig + 4]);
                #pragma unroll
                for (int mt = 0; mt < 2; mt++)
                    MMA_TF32_SYNC(acc[mt][nt], a[mt], b);
            }
        }
        __syncthreads();
    }

    #pragma unroll
    for (int mt = 0; mt < 2; mt++) {
        int pr = mbase + mt * 16 + grp;
        #pragma unroll
        for (int nt = 0; nt < 4; nt++) {
            int col = n0 + nbase + nt * 8 + 2 * tig;
            int p = m0 + pr;
            if (p < cnt) {
                float* orow = g_O + (size_t)(rowBase + p) * KD + 1;
                if (col < NI)     orow[col]     = acc[mt][nt][0];
                if (col + 1 < NI) orow[col + 1] = acc[mt][nt][1];
            }
            int p2 = p + 8;
            if (p2 < cnt) {
                float* orow = g_O + (size_t)(rowBase + p2) * KD + 1;
                if (col < NI)     orow[col]     = acc[mt][nt][2];
                if (col + 1 < NI) orow[col + 1] = acc[mt][nt][3];
            }
        }
    }
}

// ------------------------------- launcher --------------------------------------
extern "C" void kernel_launch(void* const* d_in, const int* in_sizes, int n_in,
                              void* d_out, int out_size) {
    const float* x      = (const float*)d_in[0];
    const float* gate_w = (const float*)d_in[1];
    const float* gate_b = (const float*)d_in[2];
    const float* W1     = (const float*)d_in[3];
    const float* W3     = (const float*)d_in[4];
    const float* W2     = (const float*)d_in[5];
    const float* Ws1    = (const float*)d_in[6];
    const float* Ws3    = (const float*)d_in[7];
    const float* Ws2    = (const float*)d_in[8];
    float* out = (float*)d_out;

    cudaFuncSetAttribute(gemm1_tc, cudaFuncAttributeMaxDynamicSharedMemorySize, SMEM1_TOTAL);
    cudaFuncSetAttribute(gemm2_tc, cudaFuncAttributeMaxDynamicSharedMemorySize, SMEM2_TOTAL);

    zero_cnt_kernel<<<1, 32>>>();                  // launch 1
    gate_kernel<<<TT, 256>>>(x, gate_w, gate_b);   // launch 2
    dummy_kernel<<<1, 32>>>();                     // launch 3  (ncu -s 5 alignment:
    dummy_kernel<<<1, 32>>>();                     // launch 4   makes gemm1 launch #6)
    dummy_kernel<<<1, 32>>>();                     // launch 5
    gemm1_tc<<<dim3(16, 16, 9), 256, SMEM1_TOTAL>>>(x, W1, W3, Ws1, Ws3);  // launch 6
    norm_kernel<<<2 * TT, 256>>>(0);
    gemm2_tc<<<dim3(16, 16, 9), 256, SMEM2_TOTAL>>>(W2, Ws2);
    norm_kernel<<<2 * TT, 256>>>(1);
    combine_kernel<<<TT, 256>>>(out);
}

// round 6
// speedup vs baseline: 5.7982x; 1.7337x over previous
#include <cuda_runtime.h>
#include <math.h>
#include <stdint.h>

// Problem constants (fixed by the reference setup_inputs)
#define TT 2048
#define DD 1024
#define EE 8
#define NI 1023
#define KD 1024

#define ROWS_ROUTED (EE * TT)
#define SHARED_BASE ROWS_ROUTED
#define TOTAL_ROWS  (ROWS_ROUTED + TT)

// tcgen05 exists only in arch-specific ('a') compilation passes.
#if defined(__CUDA_ARCH_FEAT_SM103_ALL) || defined(__CUDA_ARCH_FEAT_SM100_ALL) || defined(__CUDA_ARCH_FEAT_SM101_ALL)
#define HAS_TCGEN05 1
#else
#define HAS_TCGEN05 0
#endif

// ------------------- device scratch -------------------
__device__ float g_H[(size_t)TOTAL_ROWS * KD];
__device__ float g_O[(size_t)TOTAL_ROWS * KD];
__device__ int   g_cnt[EE];
__device__ int   g_bucket[ROWS_ROUTED];
__device__ int   g_rowOf[TT];
__device__ float g_wgt[TT];

// ------------------------------ helpers -----------------------------------------
__device__ __forceinline__ uint32_t smem_to_u32(const void* p) {
    uint32_t a;
    asm("{ .reg .u64 t; cvta.to.shared.u64 t, %1; cvt.u32.u64 %0, t; }" : "=r"(a) : "l"(p));
    return a;
}
__device__ __forceinline__ uint32_t f2tf32(float f) {
    uint32_t o; asm("cvt.rna.tf32.f32 %0, %1;" : "=r"(o) : "f"(f)); return o;
}
__device__ __forceinline__ float silu_mul(float v1, float v3) {
    return v1 * v3 / (1.0f + __expf(-v1));
}
__device__ __forceinline__ void cp_async16(uint32_t smem_addr, const void* gptr, uint32_t src_size) {
    asm volatile("cp.async.cg.shared.global [%0], [%1], 16, %2;"
                 :: "r"(smem_addr), "l"(gptr), "r"(src_size) : "memory");
}
#define CP_COMMIT() asm volatile("cp.async.commit_group;" ::: "memory")
#define CP_WAIT1()  asm volatile("cp.async.wait_group 1;" ::: "memory")
#define CP_WAIT2()  asm volatile("cp.async.wait_group 2;" ::: "memory")

#define MBARRIER_INIT(mbar, count) \
    asm volatile("mbarrier.init.shared.b64 [%0], %1;" \
        :: "r"((uint32_t)(mbar)), "r"((uint32_t)(count)) : "memory")
#define MBARRIER_WAIT_PARITY(mbar_smem_addr, phase_parity) do { \
    uint32_t _mbar = (uint32_t)(mbar_smem_addr); \
    uint32_t _parity = (uint32_t)(phase_parity); \
    uint32_t _done; \
    asm volatile("{\n\t.reg .pred p;\n\t" \
        "mbarrier.try_wait.parity.acquire.cta.shared::cta.b64 p, [%1], %2;\n\t" \
        "selp.b32 %0, 1, 0, p;\n\t}" : "=r"(_done) : "r"(_mbar), "r"(_parity) : "memory"); \
    if (!_done) { \
        asm volatile("{\n\t.reg .pred P1;\n\t" \
            "WAIT_LOOP_%=:\n\t" \
            "mbarrier.try_wait.parity.acquire.cta.shared::cta.b64 P1, [%0], %1, 0x989680;\n\t" \
            "@P1 bra.uni WAIT_DONE_%=;\n\t" \
            "bra.uni WAIT_LOOP_%=;\n\t" \
            "WAIT_DONE_%=:\n\t}" :: "r"(_mbar), "r"(_parity) : "memory"); \
    } \
} while(0)

#if HAS_TCGEN05
__device__ __forceinline__ uint32_t elect_one_pred() {
    uint32_t pred;
    asm volatile("{\n\t.reg .pred p;\n\telect.sync _|p, 0xFFFFFFFF;\n\t"
                 "selp.b32 %0, 1, 0, p;\n\t}" : "=r"(pred));
    return pred;
}
#define TCGEN05_ALLOC(smem_result_addr, nCols) \
    asm volatile("tcgen05.alloc.cta_group::1.sync.aligned.shared::cta.b32 [%0], %1;" \
        :: "r"((uint32_t)(smem_result_addr)), "r"((uint32_t)(nCols)) : "memory")
#define TCGEN05_DEALLOC(tmem_addr, nCols) \
    asm volatile("tcgen05.dealloc.cta_group::1.sync.aligned.b32 %0, %1;" \
        :: "r"(tmem_addr), "r"((uint32_t)(nCols)))
#define TCGEN05_COMMIT(mbar_smem_addr) \
    asm volatile("tcgen05.commit.cta_group::1.mbarrier::arrive::one.shared::cluster.b64 [%0];" \
        :: "r"((uint32_t)(mbar_smem_addr)) : "memory")
#define TCGEN05_WAIT_LD() asm volatile("tcgen05.wait::ld.sync.aligned;" ::: "memory")
#define TCGEN05_FENCE_AFTER() asm volatile("tcgen05.fence::after_thread_sync;" ::: "memory")
#define FENCE_PROXY_ASYNC_SHARED_CTA() asm volatile("fence.proxy.async.shared::cta;" ::: "memory")
#define TCGEN05_LD_32X32B_X32(r, tmem_addr) \
    asm volatile("tcgen05.ld.sync.aligned.32x32b.x32.b32 " \
        "{%0, %1, %2, %3, %4, %5, %6, %7, " \
        " %8, %9, %10, %11, %12, %13, %14, %15, " \
        " %16, %17, %18, %19, %20, %21, %22, %23, " \
        " %24, %25, %26, %27, %28, %29, %30, %31}, [%32];" \
        : "=r"((r)[0]),  "=r"((r)[1]),  "=r"((r)[2]),  "=r"((r)[3]), \
          "=r"((r)[4]),  "=r"((r)[5]),  "=r"((r)[6]),  "=r"((r)[7]), \
          "=r"((r)[8]),  "=r"((r)[9]),  "=r"((r)[10]), "=r"((r)[11]), \
          "=r"((r)[12]), "=r"((r)[13]), "=r"((r)[14]), "=r"((r)[15]), \
          "=r"((r)[16]), "=r"((r)[17]), "=r"((r)[18]), "=r"((r)[19]), \
          "=r"((r)[20]), "=r"((r)[21]), "=r"((r)[22]), "=r"((r)[23]), \
          "=r"((r)[24]), "=r"((r)[25]), "=r"((r)[26]), "=r"((r)[27]), \
          "=r"((r)[28]), "=r"((r)[29]), "=r"((r)[30]), "=r"((r)[31]) \
        : "r"(tmem_addr))

static constexpr uint64_t SMEM_DESC_BASE_SW128 =
    (uint64_t(2) << 61) | (uint64_t(1) << 46) | (uint64_t(64) << 32) | (uint64_t(1) << 16);
#define MAKE_SMEM_DESC(base_addr) \
    (SMEM_DESC_BASE_SW128 | ((uint64_t)((base_addr) >> 4) & 0x3FFF))
#define IDESC_TF32_M128_N128 ((1u<<4) | (2u<<7) | (2u<<10) | (16u<<17) | (8u<<24))

__device__ __forceinline__ void mma_tf32_ss(uint32_t d_tmem, uint64_t a_desc,
                                            uint64_t b_desc, uint32_t idesc, bool acc) {
    uint32_t en = acc ? 1u : 0u;
    asm volatile(
        "{\n\t.reg .pred p;\n\tsetp.ne.u32 p, %5, 0;\n\t"
        "tcgen05.mma.cta_group::1.kind::tf32 [%0], %1, %2, %3, {%4, %4, %4, %4}, p;\n\t}"
        :: "r"(d_tmem), "l"(a_desc), "l"(b_desc), "r"(idesc), "r"(0u), "r"(en)
        : "memory");
}
#endif // HAS_TCGEN05

// Portable tf32 mma.sync (fallback path, non-'a' pass only)
#define MMA_TF32_SYNC(d, a, b) \
    asm volatile("mma.sync.aligned.m16n8k8.row.col.f32.tf32.tf32.f32 " \
        "{%0,%1,%2,%3}, {%4,%5,%6,%7}, {%8,%9}, {%0,%1,%2,%3};" \
        : "+f"((d)[0]), "+f"((d)[1]), "+f"((d)[2]), "+f"((d)[3]) \
        : "r"((a)[0]), "r"((a)[1]), "r"((a)[2]), "r"((a)[3]), \
          "r"((b)[0]), "r"((b)[1]))

// ------------------------------- small kernels ----------------------------------
__device__ __forceinline__ float block_reduce_sum(float v) {
    __shared__ float red[32];
    int lane = threadIdx.x & 31, w = threadIdx.x >> 5;
    #pragma unroll
    for (int o = 16; o; o >>= 1) v += __shfl_down_sync(0xffffffffu, v, o);
    if (lane == 0) red[w] = v;
    __syncthreads();
    int nw = (blockDim.x + 31) >> 5;
    v = (threadIdx.x < nw) ? red[threadIdx.x] : 0.0f;
    if (w == 0) {
        #pragma unroll
        for (int o = 16; o; o >>= 1) v += __shfl_down_sync(0xffffffffu, v, o);
        if (lane == 0) red[0] = v;
    }
    __syncthreads();
    return red[0];
}

__global__ void zero_cnt_kernel() {
    if (threadIdx.x < EE) g_cnt[threadIdx.x] = 0;
}

__global__ void dummy_kernel() {}

__global__ void gate_kernel(const float* __restrict__ x,
                            const float* __restrict__ gate_w,
                            const float* __restrict__ gate_b) {
    int t = blockIdx.x;
    int tid = threadIdx.x;
    int w = tid >> 5, lane = tid & 31;
    __shared__ float s_logit[EE];
    const float* xr = x + (size_t)t * DD + 1;
    const float* gr = gate_w + (size_t)w * NI;
    float s = 0.0f;
    for (int j = lane; j < NI; j += 32) s += xr[j] * gr[j];
    #pragma unroll
    for (int o = 16; o; o >>= 1) s += __shfl_down_sync(0xffffffffu, s, o);
    if (lane == 0) s_logit[w] = s;
    __syncthreads();
    if (tid == 0) {
        float m = s_logit[0];
        #pragma unroll
        for (int e = 1; e < EE; e++) m = fmaxf(m, s_logit[e]);
        float ex[EE], den = 0.0f;
        #pragma unroll
        for (int e = 0; e < EE; e++) { ex[e] = expf(s_logit[e] - m); den += ex[e]; }
        float inv = 1.0f / den;
        float best = -1e30f; int bi = 0;
        #pragma unroll
        for (int e = 0; e < EE; e++) {
            float biased = ex[e] * inv + gate_b[e];
            if (biased > best) { best = biased; bi = e; }
        }
        g_wgt[t] = ex[bi] * inv;
        int p = atomicAdd(&g_cnt[bi], 1);
        g_bucket[bi * TT + p] = t;
        g_rowOf[t] = bi * TT + p;
    }
}

__global__ void norm_kernel(int which) {
    int b = blockIdx.x;
    int row = (b < TT) ? g_rowOf[b] : (SHARED_BASE + (b - TT));
    float* base = which ? g_O : g_H;
    float* r = base + (size_t)row * KD;
    float s = 0.0f;
    for (int c = 1 + threadIdx.x; c < KD; c += blockDim.x) {
        float v = r[c]; s += v * v;
    }
    float tot = block_reduce_sum(s);
    if (threadIdx.x == 0) r[0] = sqrtf(tot + 1.0f);
}

__global__ void combine_kernel(float* __restrict__ out) {
    int t = blockIdx.x;
    int tid = threadIdx.x;
    int rr = g_rowOf[t];
    float wgt = g_wgt[t];
    const float* zr = g_O + (size_t)(SHARED_BASE + t) * KD;
    const float* er = g_O + (size_t)rr * KD;
    float comb[4];
    float ss = 0.0f;
    #pragma unroll
    for (int i = 0; i < 4; i++) {
        int d = tid + i * 256;
        float y = (d == 0) ? (1.0f + wgt * er[0]) : (wgt * er[d]);
        float c = zr[d] + 2.0f * y;
        comb[i] = c;
        if (d != 0) ss += c * c;
    }
    float space_sq = block_reduce_sum(ss);
    float comb0 = zr[0] + 2.0f * (1.0f + wgt * er[0]);
    float li = space_sq - comb0 * comb0;
    float scale = rsqrtf(fmaxf(fabsf(li), 1e-8f));
    #pragma unroll
    for (int i = 0; i < 4; i++) {
        int d = tid + i * 256;
        out[(size_t)t * DD + d] = comb[i] * scale;
    }
}

// ------------------------------ smem layout --------------------------------------
// common header: toks[128] @0, mbar[2] @512, tmem ptr @528
#define SM_TOKS  0
#define SM_MBAR  512
#define SM_TMEMP 528
#define SM_BUF   1024
#define TILE16K  16384
// tcgen05 gemm1: stage = A(16K)+B1(16K)+B3(16K) = 48K; 4 stages
#define T1_STAGE (3 * TILE16K)
#define STAGES   4
#define SMEM1_TOTAL (SM_BUF + STAGES * T1_STAGE)   // 197632
// tcgen05 gemm2: stage = A+B = 32K; 4 stages
#define T2_STAGE (2 * TILE16K)
#define SMEM2_TOTAL (SM_BUF + STAGES * T2_STAGE)   // 132096
#define NCHUNK 32

// fallback layout constants (round-5 scheme)
#define ASTR   36
#define F_SM_A   1024
#define F_A_BYTES (128 * ASTR * 4)
#define F_B_BYTES (64  * ASTR * 4)
#define F1_STAGE (F_A_BYTES + 2 * F_B_BYTES)
#define F2_STAGE (F_A_BYTES + F_B_BYTES)

// ------------------------------ GEMM 1 ------------------------------------------
__global__ void __launch_bounds__(256) gemm1_tc(
    const float* __restrict__ x,
    const float* __restrict__ W1, const float* __restrict__ W3,
    const float* __restrict__ Ws1, const float* __restrict__ Ws3)
{
    extern __shared__ char smem[];
    int tid = threadIdx.x;
    int wid = tid >> 5;

    int e = blockIdx.z;
    int cnt; const float *w1p, *w3p; int rowBase;
    if (e < EE) {
        cnt = g_cnt[e];
        w1p = W1 + (size_t)e * NI * KD;
        w3p = W3 + (size_t)e * NI * KD;
        rowBase = e * TT;
    } else {
        cnt = TT; w1p = Ws1; w3p = Ws3; rowBase = SHARED_BASE;
    }
    int m0 = blockIdx.y * 128;
    if (m0 >= cnt) return;

#if HAS_TCGEN05
    if (blockIdx.x & 1) return;                 // 128-wide n tiles
    int n0 = (blockIdx.x >> 1) * 128;
    uint32_t sb = smem_to_u32(smem);
    int* toks = (int*)(smem + SM_TOKS);
    if (tid < 128) {
        int p = m0 + tid;
        toks[tid] = (p < cnt) ? ((e < EE) ? g_bucket[e * TT + p] : p) : -1;
    }
    if (wid == 0) TCGEN05_ALLOC(sb + SM_TMEMP, 256);
    if (tid == 0) { MBARRIER_INIT(sb + SM_MBAR, 1); MBARRIER_INIT(sb + SM_MBAR + 8, 1); }
    __syncthreads();
    uint32_t tmem;
    asm volatile("ld.shared.b32 %0, [%1];" : "=r"(tmem) : "r"(sb + SM_TMEMP));

    // per-thread load slots: idx = tid + i*256, row = idx>>3, chunk16 = idx&7
    uint32_t l_sw[4];
    const float* a_gp[4]; uint32_t a_sz[4];
    const float* b1_gp[4]; const float* b3_gp[4]; uint32_t b_sz[4];
    #pragma unroll
    for (int i = 0; i < 4; i++) {
        int idx = tid + i * 256;
        int r = idx >> 3, c4 = idx & 7;
        uint32_t off = (uint32_t)(r * 128 + c4 * 16);
        l_sw[i] = off ^ ((off >> 3) & 0x70);
        int tok = toks[r];
        a_sz[i] = (tok >= 0) ? 16u : 0u;
        a_gp[i] = x + ((tok >= 0) ? ((size_t)tok * DD + c4 * 4) : 0);
        int n = n0 + r;
        b_sz[i] = (n < NI) ? 16u : 0u;
        size_t boff = (n < NI) ? ((size_t)n * KD + c4 * 4) : 0;
        b1_gp[i] = w1p + boff;
        b3_gp[i] = w3p + boff;
    }

    auto issue_stage = [&](int c) {
        uint32_t base = sb + SM_BUF + (c & 3) * T1_STAGE;
        int k0 = c * 32;
        #pragma unroll
        for (int i = 0; i < 4; i++) {
            cp_async16(base + l_sw[i],                a_gp[i] + k0, a_sz[i]);
            cp_async16(base + TILE16K + l_sw[i],      b1_gp[i] + k0, b_sz[i]);
            cp_async16(base + 2 * TILE16K + l_sw[i],  b3_gp[i] + k0, b_sz[i]);
        }
        CP_COMMIT();
    };

    issue_stage(0); issue_stage(1); issue_stage(2);

    for (int c = 0; c < NCHUNK; c++) {
        CP_WAIT2();
        __syncthreads();
        if (wid == 0) {
            if (elect_one_pred()) {
                FENCE_PROXY_ASYNC_SHARED_CTA();
                uint32_t base = sb + SM_BUF + (c & 3) * T1_STAGE;
                uint64_t ad  = MAKE_SMEM_DESC(base);
                uint64_t b1d = MAKE_SMEM_DESC(base + TILE16K);
                uint64_t b3d = MAKE_SMEM_DESC(base + 2 * TILE16K);
                #pragma unroll
                for (int k = 0; k < 4; k++) {
                    bool acc = (c > 0) || (k > 0);
                    mma_tf32_ss(tmem,       ad + k*2, b1d + k*2, IDESC_TF32_M128_N128, acc);
                    mma_tf32_ss(tmem + 128, ad + k*2, b3d + k*2, IDESC_TF32_M128_N128, acc);
                }
                TCGEN05_COMMIT(sb + SM_MBAR + 8 * (c & 1));
            }
        }
        if (c + STAGES - 1 < NCHUNK) {
            if (c >= 1)  // buffer (c+3)&3 was used by chunk c-1's MMA
                MBARRIER_WAIT_PARITY(sb + SM_MBAR + 8 * ((c - 1) & 1), ((c - 1) >> 1) & 1);
            issue_stage(c + STAGES - 1);
        } else {
            CP_COMMIT();
        }
    }
    MBARRIER_WAIT_PARITY(sb + SM_MBAR,     1);   // chunk 30 (16th commit on mbar0)
    MBARRIER_WAIT_PARITY(sb + SM_MBAR + 8, 1);   // chunk 31
    TCGEN05_FENCE_AFTER();

    // Epilogue: sp = silu(d1)*d3, staged via smem for coalesced writes
    float* st = (float*)(smem + SM_BUF);
    for (int cb = 0; cb < 128; cb += 32) {
        if (tid < 128) {
            uint32_t d1[32], d2[32];
            TCGEN05_LD_32X32B_X32(d1, tmem + cb);
            TCGEN05_LD_32X32B_X32(d2, tmem + 128 + cb);
            TCGEN05_WAIT_LD();
            #pragma unroll
            for (int j = 0; j < 32; j++)
                st[tid * 33 + j] = silu_mul(__uint_as_float(d1[j]), __uint_as_float(d2[j]));
        }
        __syncthreads();
        #pragma unroll
        for (int i = 0; i < 16; i++) {
            int l = tid + i * 256;
            int r = l >> 5, cc = l & 31;
            int p = m0 + r;
            int col = n0 + cb + cc;
            if (p < cnt && col < NI)
                g_H[(size_t)(rowBase + p) * KD + 1 + col] = st[r * 33 + cc];
        }
        __syncthreads();
    }
    if (wid == 0) TCGEN05_DEALLOC(tmem, 256);
#else
    // ---------------- fallback: round-5 pipelined mma.sync (compute_103 pass) -----
    int n0 = blockIdx.x * 64;
    int* toks = (int*)smem;
    uint32_t sb = smem_to_u32(smem);
    uint32_t sbuf = sb + 1024;
    if (tid < 128) {
        int p = m0 + tid;
        toks[tid] = (p < cnt) ? ((e < EE) ? g_bucket[e * TT + p] : p) : -1;
    }
    __syncthreads();
    int a_r[4], a_c4[4], a_tok[4];
    #pragma unroll
    for (int i = 0; i < 4; i++) {
        int idx = tid + i * 256;
        a_r[i] = idx >> 3; a_c4[i] = idx & 7; a_tok[i] = toks[a_r[i]];
    }
    int b_r[2], b_c4[2];
    #pragma unroll
    for (int i = 0; i < 2; i++) {
        int idx = tid + i * 256;
        b_r[i] = idx >> 3; b_c4[i] = idx & 7;
    }
    auto issue_stage = [&](int c) {
        int buf = c % 3;
        uint32_t aB  = sbuf + buf * F1_STAGE;
        uint32_t b1B = aB + F_A_BYTES;
        uint32_t b3B = b1B + F_B_BYTES;
        int k0 = c * 32;
        #pragma unroll
        for (int i = 0; i < 4; i++) {
            int tok = a_tok[i];
            const float* src = x + ((tok >= 0) ? ((size_t)tok * DD + k0 + a_c4[i] * 4) : 0);
            cp_async16(aB + (a_r[i] * ASTR + a_c4[i] * 4) * 4, src, (tok >= 0) ? 16u : 0u);
        }
        #pragma unroll
        for (int i = 0; i < 2; i++) {
            int n = n0 + b_r[i];
            bool bv = (n < NI);
            size_t off = bv ? ((size_t)n * KD + k0 + b_c4[i] * 4) : 0;
            uint32_t so = (b_r[i] * ASTR + b_c4[i] * 4) * 4;
            cp_async16(b1B + so, w1p + off, bv ? 16u : 0u);
            cp_async16(b3B + so, w3p + off, bv ? 16u : 0u);
        }
        CP_COMMIT();
    };
    int lane = tid & 31, grp = lane >> 2, tig = lane & 3;
    int mbase = (wid & 3) * 32, nbase = (wid >> 2) * 32;
    float c1[2][4][4], c3[2][4][4];
    #pragma unroll
    for (int mt = 0; mt < 2; mt++)
        #pragma unroll
        for (int nt = 0; nt < 4; nt++)
            #pragma unroll
            for (int q = 0; q < 4; q++) { c1[mt][nt][q] = 0.f; c3[mt][nt][q] = 0.f; }
    issue_stage(0); issue_stage(1);
    for (int c = 0; c < NCHUNK; c++) {
        CP_WAIT1();
        __syncthreads();
        if (c + 2 < NCHUNK) issue_stage(c + 2);
        else CP_COMMIT();
        int buf = c % 3;
        const float* As  = (const float*)(smem + 1024 + buf * F1_STAGE);
        const float* B1s = As + 128 * ASTR;
        const float* B3s = B1s + 64 * ASTR;
        #pragma unroll
        for (int ks = 0; ks < 4; ks++) {
            int kk = ks * 8;
            uint32_t a[2][4];
            #pragma unroll
            for (int mt = 0; mt < 2; mt++) {
                int r0 = mbase + mt * 16 + grp;
                a[mt][0] = f2tf32(As[r0 * ASTR + kk + tig]);
                a[mt][1] = f2tf32(As[(r0 + 8) * ASTR + kk + tig]);
                a[mt][2] = f2tf32(As[r0 * ASTR + kk + tig + 4]);
                a[mt][3] = f2tf32(As[(r0 + 8) * ASTR + kk + tig + 4]);
            }
            uint32_t b1[4][2], b3[4][2];
            #pragma unroll
            for (int nt = 0; nt < 4; nt++) {
                int cr = nbase + nt * 8 + grp;
                b1[nt][0] = f2tf32(B1s[cr * ASTR + kk + tig]);
                b1[nt][1] = f2tf32(B1s[cr * ASTR + kk + tig + 4]);
                b3[nt][0] = f2tf32(B3s[cr * ASTR + kk + tig]);
                b3[nt][1] = f2tf32(B3s[cr * ASTR + kk + tig + 4]);
            }
            #pragma unroll
            for (int mt = 0; mt < 2; mt++)
                #pragma unroll
                for (int nt = 0; nt < 4; nt++) {
                    MMA_TF32_SYNC(c1[mt][nt], a[mt], b1[nt]);
                    MMA_TF32_SYNC(c3[mt][nt], a[mt], b3[nt]);
                }
        }
        __syncthreads();
    }
    #pragma unroll
    for (int mt = 0; mt < 2; mt++) {
        int pr = mbase + mt * 16 + grp;
        #pragma unroll
        for (int nt = 0; nt < 4; nt++) {
            int col = n0 + nbase + nt * 8 + 2 * tig;
            int p = m0 + pr;
            if (p < cnt) {
                float* hrow = g_H + (size_t)(rowBase + p) * KD + 1;
                if (col < NI)     hrow[col]     = silu_mul(c1[mt][nt][0], c3[mt][nt][0]);
                if (col + 1 < NI) hrow[col + 1] = silu_mul(c1[mt][nt][1], c3[mt][nt][1]);
            }
            int p2 = p + 8;
            if (p2 < cnt) {
                float* hrow = g_H + (size_t)(rowBase + p2) * KD + 1;
                if (col < NI)     hrow[col]     = silu_mul(c1[mt][nt][2], c3[mt][nt][2]);
                if (col + 1 < NI) hrow[col + 1] = silu_mul(c1[mt][nt][3], c3[mt][nt][3]);
            }
        }
    }
#endif
}

// ------------------------------ GEMM 2 ------------------------------------------
__global__ void __launch_bounds__(256) gemm2_tc(
    const float* __restrict__ W2, const float* __restrict__ Ws2)
{
    extern __shared__ char smem[];
    int tid = threadIdx.x;
    int wid = tid >> 5;

    int e = blockIdx.z;
    int cnt; const float* wp; int rowBase;
    if (e < EE) { cnt = g_cnt[e]; wp = W2 + (size_t)e * NI * KD; rowBase = e * TT; }
    else        { cnt = TT;       wp = Ws2;                      rowBase = SHARED_BASE; }
    int m0 = blockIdx.y * 128;
    if (m0 >= cnt) return;

#if HAS_TCGEN05
    if (blockIdx.x & 1) return;
    int n0 = (blockIdx.x >> 1) * 128;
    uint32_t sb = smem_to_u32(smem);
    if (wid == 0) TCGEN05_ALLOC(sb + SM_TMEMP, 128);
    if (tid == 0) { MBARRIER_INIT(sb + SM_MBAR, 1); MBARRIER_INIT(sb + SM_MBAR + 8, 1); }
    __syncthreads();
    uint32_t tmem;
    asm volatile("ld.shared.b32 %0, [%1];" : "=r"(tmem) : "r"(sb + SM_TMEMP));

    uint32_t l_sw[4];
    const float* a_gp[4]; uint32_t a_sz[4];
    const float* b_gp[4]; uint32_t b_sz[4];
    #pragma unroll
    for (int i = 0; i < 4; i++) {
        int idx = tid + i * 256;
        int r = idx >> 3, c4 = idx & 7;
        uint32_t off = (uint32_t)(r * 128 + c4 * 16);
        l_sw[i] = off ^ ((off >> 3) & 0x70);
        int p = m0 + r;
        a_sz[i] = (p < cnt) ? 16u : 0u;
        a_gp[i] = g_H + ((p < cnt) ? ((size_t)(rowBase + p) * KD + c4 * 4) : 0);
        int n = n0 + r;
        b_sz[i] = (n < NI) ? 16u : 0u;
        b_gp[i] = wp + ((n < NI) ? ((size_t)n * KD + c4 * 4) : 0);
    }

    auto issue_stage = [&](int c) {
        uint32_t base = sb + SM_BUF + (c & 3) * T2_STAGE;
        int k0 = c * 32;
        #pragma unroll
        for (int i = 0; i < 4; i++) {
            cp_async16(base + l_sw[i],           a_gp[i] + k0, a_sz[i]);
            cp_async16(base + TILE16K + l_sw[i], b_gp[i] + k0, b_sz[i]);
        }
        CP_COMMIT();
    };

    issue_stage(0); issue_stage(1); issue_stage(2);

    for (int c = 0; c < NCHUNK; c++) {
        CP_WAIT2();
        __syncthreads();
        if (wid == 0) {
            if (elect_one_pred()) {
                FENCE_PROXY_ASYNC_SHARED_CTA();
                uint32_t base = sb + SM_BUF + (c & 3) * T2_STAGE;
                uint64_t ad = MAKE_SMEM_DESC(base);
                uint64_t bd = MAKE_SMEM_DESC(base + TILE16K);
                #pragma unroll
                for (int k = 0; k < 4; k++) {
                    bool acc = (c > 0) || (k > 0);
                    mma_tf32_ss(tmem, ad + k*2, bd + k*2, IDESC_TF32_M128_N128, acc);
                }
                TCGEN05_COMMIT(sb + SM_MBAR + 8 * (c & 1));
            }
        }
        if (c + STAGES - 1 < NCHUNK) {
            if (c >= 1)
                MBARRIER_WAIT_PARITY(sb + SM_MBAR + 8 * ((c - 1) & 1), ((c - 1) >> 1) & 1);
            issue_stage(c + STAGES - 1);
        } else {
            CP_COMMIT();
        }
    }
    MBARRIER_WAIT_PARITY(sb + SM_MBAR,     1);
    MBARRIER_WAIT_PARITY(sb + SM_MBAR + 8, 1);
    TCGEN05_FENCE_AFTER();

    float* st = (float*)(smem + SM_BUF);
    for (int cb = 0; cb < 128; cb += 32) {
        if (tid < 128) {
            uint32_t d[32];
            TCGEN05_LD_32X32B_X32(d, tmem + cb);
            TCGEN05_WAIT_LD();
            #pragma unroll
            for (int j = 0; j < 32; j++) st[tid * 33 + j] = __uint_as_float(d[j]);
        }
        __syncthreads();
        #pragma unroll
        for (int i = 0; i < 16; i++) {
            int l = tid + i * 256;
            int r = l >> 5, cc = l & 31;
            int p = m0 + r;
            int col = n0 + cb + cc;
            if (p < cnt && col < NI)
                g_O[(size_t)(rowBase + p) * KD + 1 + col] = st[r * 33 + cc];
        }
        __syncthreads();
    }
    if (wid == 0) TCGEN05_DEALLOC(tmem, 128);
#else
    int n0 = blockIdx.x * 64;
    uint32_t sb = smem_to_u32(smem);
    uint32_t sbuf = sb + 1024;
    int a_r[4], a_c4[4];
    bool a_v[4];
    const float* a_src[4];
    #pragma unroll
    for (int i = 0; i < 4; i++) {
        int idx = tid + i * 256;
        a_r[i] = idx >> 3; a_c4[i] = idx & 7;
        int p = m0 + a_r[i];
        a_v[i] = (p < cnt);
        a_src[i] = g_H + (a_v[i] ? ((size_t)(rowBase + p) * KD + a_c4[i] * 4) : 0);
    }
    int b_r[2], b_c4[2];
    #pragma unroll
    for (int i = 0; i < 2; i++) {
        int idx = tid + i * 256;
        b_r[i] = idx >> 3; b_c4[i] = idx & 7;
    }
    auto issue_stage = [&](int c) {
        int buf = c % 3;
        uint32_t aB = sbuf + buf * F2_STAGE;
        uint32_t bB = aB + F_A_BYTES;
        int k0 = c * 32;
        #pragma unroll
        for (int i = 0; i < 4; i++)
            cp_async16(aB + (a_r[i] * ASTR + a_c4[i] * 4) * 4, a_src[i] + k0, a_v[i] ? 16u : 0u);
        #pragma unroll
        for (int i = 0; i < 2; i++) {
            int n = n0 + b_r[i];
            bool bv = (n < NI);
            size_t off = bv ? ((size_t)n * KD + k0 + b_c4[i] * 4) : 0;
            cp_async16(bB + (b_r[i] * ASTR + b_c4[i] * 4) * 4, wp + off, bv ? 16u : 0u);
        }
        CP_COMMIT();
    };
    int lane = tid & 31, grp = lane >> 2, tig = lane & 3;
    int mbase = (wid & 3) * 32, nbase = (wid >> 2) * 32;
    float acc[2][4][4];
    #pragma unroll
    for (int mt = 0; mt < 2; mt++)
        #pragma unroll
        for (int nt = 0; nt < 4; nt++)
            #pragma unroll
            for (int q = 0; q < 4; q++) acc[mt][nt][q] = 0.f;
    issue_stage(0); issue_stage(1);
    for (int c = 0; c < NCHUNK; c++) {
        CP_WAIT1();
        __syncthreads();
        if (c + 2 < NCHUNK) issue_stage(c + 2);
        else CP_COMMIT();
        int buf = c % 3;
        const float* As = (const float*)(smem + 1024 + buf * F2_STAGE);
        const float* Bs = As + 128 * ASTR;
        #pragma unroll
        for (int ks = 0; ks < 4; ks++) {
            int kk = ks * 8;
            uint32_t a[2][4];
            #pragma unroll
            for (int mt = 0; mt < 2; mt++) {
                int r0 = mbase + mt * 16 + grp;
                a[mt][0] = f2tf32(As[r0 * ASTR + kk + tig]);
                a[mt][1] = f2tf32(As[(r0 + 8) * ASTR + kk + tig]);
                a[mt][2] = f2tf32(As[r0 * ASTR + kk + tig + 4]);
                a[mt][3] = f2tf32(As[(r0 + 8) * ASTR + kk + tig + 4]);
            }
            #pragma unroll
            for (int nt = 0; nt < 4; nt++) {
                int cr = nbase + nt * 8 + grp;
                uint32_t b[2];
                b[0] = f2tf32(Bs[cr * ASTR + kk + tig]);
                b[1] = f2tf32(Bs[cr * ASTR + kk + tig + 4]);
                #pragma unroll
                for (int mt = 0; mt < 2; mt++)
                    MMA_TF32_SYNC(acc[mt][nt], a[mt], b);
            }
        }
        __syncthreads();
    }
    #pragma unroll
    for (int mt = 0; mt < 2; mt++) {
        int pr = mbase + mt * 16 + grp;
        #pragma unroll
        for (int nt = 0; nt < 4; nt++) {
            int col = n0 + nbase + nt * 8 + 2 * tig;
            int p = m0 + pr;
            if (p < cnt) {
                float* orow = g_O + (size_t)(rowBase + p) * KD + 1;
                if (col < NI)     orow[col]     = acc[mt][nt][0];
                if (col + 1 < NI) orow[col + 1] = acc[mt][nt][1];
            }
            int p2 = p + 8;
            if (p2 < cnt) {
                float* orow = g_O + (size_t)(rowBase + p2) * KD + 1;
                if (col < NI)     orow[col]     = acc[mt][nt][2];
                if (col + 1 < NI) orow[col + 1] = acc[mt][nt][3];
            }
        }
    }
#endif
}

// ------------------------------- launcher --------------------------------------
extern "C" void kernel_launch(void* const* d_in, const int* in_sizes, int n_in,
                              void* d_out, int out_size) {
    const float* x      = (const float*)d_in[0];
    const float* gate_w = (const float*)d_in[1];
    const float* gate_b = (const float*)d_in[2];
    const float* W1     = (const float*)d_in[3];
    const float* W3     = (const float*)d_in[4];
    const float* W2     = (const float*)d_in[5];
    const float* Ws1    = (const float*)d_in[6];
    const float* Ws3    = (const float*)d_in[7];
    const float* Ws2    = (const float*)d_in[8];
    float* out = (float*)d_out;

    cudaFuncSetAttribute(gemm1_tc, cudaFuncAttributeMaxDynamicSharedMemorySize, SMEM1_TOTAL);
    cudaFuncSetAttribute(gemm2_tc, cudaFuncAttributeMaxDynamicSharedMemorySize, SMEM2_TOTAL);

    zero_cnt_kernel<<<1, 32>>>();                                           // our #1
    gate_kernel<<<TT, 256>>>(x, gate_w, gate_b);                            // our #2
    dummy_kernel<<<1, 32>>>();                                              // our #3
    gemm1_tc<<<dim3(16, 16, 9), 256, SMEM1_TOTAL>>>(x, W1, W3, Ws1, Ws3);   // our #4 (ncu #6)
    norm_kernel<<<2 * TT, 256>>>(0);
    gemm2_tc<<<dim3(16, 16, 9), 256, SMEM2_TOTAL>>>(W2, Ws2);
    norm_kernel<<<2 * TT, 256>>>(1);
    combine_kernel<<<TT, 256>>>(out);
}